// round 3
// baseline (speedup 1.0000x reference)
#include <cuda_runtime.h>
#include <math.h>

#define Bn 4
#define Tn 8192
#define Dn 1024
#define Hn 8
#define HDn 128
#define Cn 64
#define Nchunk 128
#define BTn (Bn*Tn)
#define BHn (Bn*Hn)

// ---------------- scratch (device globals; no cudaMalloc allowed) ----------
__device__ float g_v[(size_t)BTn*Dn];       // v*beta -> v' (in place)
__device__ float g_rk[(size_t)BTn*Dn];      // normalized read keys, (B,H,T,d)
__device__ float g_wkcd[(size_t)BTn*Dn];    // wk_cumdecay, (B,H,T,d)
__device__ float g_o[(size_t)BTn*Dn];       // gated per-head output, (B,T,D)
__device__ float g_attn[(size_t)BHn*Nchunk*Cn*Cn];
__device__ float g_beta[BHn*Tn];            // (B,H,T)
__device__ float g_gate[BHn*Tn];
__device__ float g_dec[BHn*Tn];             // decay, then in-chunk cumsum (in place)

__device__ __forceinline__ float warp_sum(float v) {
#pragma unroll
  for (int o = 16; o > 0; o >>= 1) v += __shfl_xor_sync(0xffffffffu, v, o);
  return v;
}

// ---------------- 1) per-token projections + rk normalize ------------------
__global__ __launch_bounds__(256) void k_proj_small(
    const float* __restrict__ x, const float* __restrict__ Wg,
    const float* __restrict__ Wb, const float* __restrict__ Wa,
    const float* __restrict__ dtb, const float* __restrict__ Alog) {
  __shared__ float xs[Dn];
  int row = blockIdx.x;                  // b*T + t
  const float* xr = x + (size_t)row * Dn;
  for (int i = threadIdx.x; i < Dn; i += 256) xs[i] = xr[i];
  __syncthreads();
  int h = threadIdx.x >> 5, lane = threadIdx.x & 31;
  const float* wg = Wg + h * Dn;
  const float* wb = Wb + h * Dn;
  const float* wa = Wa + h * Dn;
  float sg = 0.f, sb = 0.f, sa = 0.f;
  for (int i = lane; i < Dn; i += 32) {
    float xv = xs[i];
    sg += xv * wg[i]; sb += xv * wb[i]; sa += xv * wa[i];
  }
  sg = warp_sum(sg); sb = warp_sum(sb); sa = warp_sum(sa);
  float ss = 0.f;
  for (int i = lane; i < HDn; i += 32) { float v = xs[h*HDn + i]; ss += v*v; }
  ss = warp_sum(ss);
  float inv = 1.0f / fmaxf(sqrtf(ss), 1e-12f);
  int b = row >> 13, t = row & (Tn - 1);
  size_t bh = (size_t)b * Hn + h;
  float* rko = g_rk + (bh * Tn + t) * HDn;
  for (int i = lane; i < HDn; i += 32) rko[i] = xs[h*HDn + i] * inv;
  if (lane == 0) {
    g_gate[bh*Tn + t] = 1.0f / (1.0f + expf(-sg));
    g_beta[bh*Tn + t] = 1.0f / (1.0f + expf(-sb));
    float z = sa + dtb[h];
    float sp = (z > 20.0f) ? z : log1pf(expf(z));
    g_dec[bh*Tn + t] = -expf(Alog[h]) * sp;
  }
}

// ---------------- 2) in-chunk cumsum of decay ------------------------------
__global__ void k_cumsum() {
  int idx = blockIdx.x;                  // bh*N + n
  int bh = idx >> 7, n = idx & (Nchunk - 1);
  size_t base = (size_t)bh * Tn + (size_t)n * Cn;
  float v = g_dec[base + threadIdx.x];
  int lane = threadIdx.x & 31, w = threadIdx.x >> 5;
#pragma unroll
  for (int o = 1; o < 32; o <<= 1) {
    float u = __shfl_up_sync(0xffffffffu, v, o);
    if (lane >= o) v += u;
  }
  __shared__ float tot;
  if (w == 0 && lane == 31) tot = v;
  __syncthreads();
  if (w == 1) v += tot;
  g_dec[base + threadIdx.x] = v;
}

// ---------------- 3) GEMM: v = x @ W_write^T, epilogue *= beta -------------
__global__ __launch_bounds__(256) void k_gemm_v(const float* __restrict__ A,
                                                const float* __restrict__ Bw) {
  __shared__ float As[8][128];
  __shared__ float Bs[8][128];
  int n0 = blockIdx.x * 128;
  int m0 = blockIdx.y * 128;
  int tid = threadIdx.x;
  int tx = tid & 15, ty = tid >> 4;
  float acc[8][8];
#pragma unroll
  for (int i = 0; i < 8; i++)
#pragma unroll
    for (int j = 0; j < 8; j++) acc[i][j] = 0.0f;
  int lrow = tid >> 1, lk4 = (tid & 1) * 4;
  const float* Ap = A + (size_t)(m0 + lrow) * Dn + lk4;
  const float* Bp = Bw + (size_t)(n0 + lrow) * Dn + lk4;
  for (int k0 = 0; k0 < Dn; k0 += 8) {
    float4 av = *(const float4*)(Ap + k0);
    float4 bv = *(const float4*)(Bp + k0);
    __syncthreads();
    As[lk4+0][lrow] = av.x; As[lk4+1][lrow] = av.y; As[lk4+2][lrow] = av.z; As[lk4+3][lrow] = av.w;
    Bs[lk4+0][lrow] = bv.x; Bs[lk4+1][lrow] = bv.y; Bs[lk4+2][lrow] = bv.z; Bs[lk4+3][lrow] = bv.w;
    __syncthreads();
#pragma unroll
    for (int kk = 0; kk < 8; kk++) {
      float a[8], b2[8];
      *(float4*)&a[0]  = *(const float4*)&As[kk][ty*8];
      *(float4*)&a[4]  = *(const float4*)&As[kk][ty*8+4];
      *(float4*)&b2[0] = *(const float4*)&Bs[kk][tx*8];
      *(float4*)&b2[4] = *(const float4*)&Bs[kk][tx*8+4];
#pragma unroll
      for (int i = 0; i < 8; i++)
#pragma unroll
        for (int j = 0; j < 8; j++) acc[i][j] += a[i] * b2[j];
    }
  }
  int h = n0 >> 7;                       // BN == head_dim, so one head per block
#pragma unroll
  for (int i = 0; i < 8; i++) {
    int m = m0 + ty*8 + i;
    int b = m >> 13, t = m & (Tn - 1);
    size_t bhT = ((size_t)(b * Hn + h)) * Tn + t;
    float beta = g_beta[bhT];
    float* vout = g_v + bhT * HDn;
#pragma unroll
    for (int j = 0; j < 8; j++) {
      int dd = tx*8 + j;
      vout[dd] = acc[i][j] * beta;
    }
  }
}

// ---------------- 4) per-chunk: M, (I+M)^-1, attn, wkcd, v' ----------------
#define K4_SMEM ((64*129 + 2*64*65 + 128 + 4*64) * 4)
__global__ __launch_bounds__(256) void k_chunk() {
  extern __shared__ float sm[];
  float* rbuf  = sm;                     // 64x129: rk tile, then scaled wk, then v
  float* Msm   = rbuf + 64*129;          // 64x65
  float* Asm   = Msm + 64*65;            // 64x65
  float* w0    = Asm + 64*65;            // 128: wk row 0
  float* decS  = w0 + 128;
  float* betaS = decS + 64;
  float* edecS = betaS + 64;
  float* beS   = edecS + 64;

  int cid = blockIdx.x;                  // bh*N + n
  int bh = cid >> 7, n = cid & (Nchunk - 1);
  int tid = threadIdx.x;
  size_t tbase = (size_t)bh * Tn + (size_t)n * Cn;
  const float* rkG = g_rk + tbase * HDn;

  for (int i = tid; i < 64*128; i += 256) {
    int c = i >> 7, d = i & 127;
    rbuf[c*129 + d] = rkG[(size_t)c*HDn + d];
  }
  if (tid < 128) w0[tid] = (n == 0) ? 0.0f : g_rk[(tbase - 1) * HDn + tid];
  if (tid >= 128 && tid < 192) {
    int c = tid - 128;
    float dv = g_dec[tbase + c];
    float bv = g_beta[tbase + c];
    float ed = expf(dv);
    decS[c] = dv; edecS[c] = ed; betaS[c] = bv; beS[c] = bv * ed;
  }
  __syncthreads();

  // M (strict lower) + A := I
  for (int idx = tid; idx < 4096; idx += 256) {
    int i = idx >> 6, j = idx & 63;
    Asm[i*65 + j] = (i == j) ? 1.0f : 0.0f;
    if (i > j) {
      const float* wi = (i == 0) ? w0 : &rbuf[(i-1)*129];
      const float* wj = (j == 0) ? w0 : &rbuf[(j-1)*129];
      float s = 0.f;
#pragma unroll 4
      for (int d = 0; d < 128; d++) s += wi[d] * wj[d];
      Msm[i*65 + j] = s * betaS[i] * expf(decS[i] - decS[j]);
    }
  }
  __syncthreads();

  // forward elimination: A = (I+M)^-1 (unit lower triangular)
  for (int i = 0; i < 63; i++) {
    int ncols = i + 1;
    int tot = (63 - i) * ncols;
    for (int idx = tid; idx < tot; idx += 256) {
      int q = idx / ncols;
      int ip = i + 1 + q;
      int k = idx - q * ncols;
      Asm[ip*65 + k] -= Msm[ip*65 + i] * Asm[i*65 + k];
    }
    __syncthreads();
  }

  // attn = (rk . wk^T) * L (incl. diag), zero above diag
  float* attnOut = g_attn + (size_t)cid * 4096;
  for (int idx = tid; idx < 4096; idx += 256) {
    int i = idx >> 6, j = idx & 63;
    float aval = 0.0f;
    if (i >= j) {
      const float* ri = &rbuf[i*129];
      const float* wj = (j == 0) ? w0 : &rbuf[(j-1)*129];
      float s = 0.f;
#pragma unroll 4
      for (int d = 0; d < 128; d++) s += ri[d] * wj[d];
      aval = s * expf(decS[i] - decS[j]);
    }
    attnOut[idx] = aval;
  }
  __syncthreads();

  // scale wk rows in place by beta*exp(dec): wk row j (j>=1) lives at rbuf row j-1
  for (int i = tid; i < 63*128; i += 256) {
    int j = i >> 7, d = i & 127;
    rbuf[j*129 + d] *= beS[j + 1];
  }
  if (tid < 128) w0[tid] *= beS[0];
  __syncthreads();

  // wkcd = A @ (wk_beta * exp(dec))
  {
    int dd = tid & 127, ch = tid >> 7;
    float* outp = g_wkcd + tbase * HDn;
    for (int c = ch; c < 64; c += 2) {
      float acc = Asm[c*65 + 0] * w0[dd];
      for (int j = 1; j <= c; j++) acc += Asm[c*65 + j] * rbuf[(j-1)*129 + dd];
      outp[(size_t)c*HDn + dd] = acc;
    }
  }
  __syncthreads();

  // load v (already *beta) into rbuf
  {
    const float* vG = g_v + tbase * HDn;
    for (int i = tid; i < 64*128; i += 256) {
      int c = i >> 7, d = i & 127;
      rbuf[c*129 + d] = vG[(size_t)c*HDn + d];
    }
  }
  __syncthreads();

  // v' = A @ v (unit diagonal), overwrite g_v
  {
    int dd = tid & 127, ch = tid >> 7;
    float* outp = g_v + tbase * HDn;
    for (int c = ch; c < 64; c += 2) {
      float acc = rbuf[c*129 + dd];
      for (int j = 0; j < c; j++) acc += Asm[c*65 + j] * rbuf[j*129 + dd];
      outp[(size_t)c*HDn + dd] = acc;
    }
  }
}

// ---------------- 5) inter-chunk recurrence, column-split x4 ---------------
#define K5_SMEM ((128*33 + 64*33 + 4096 + 64*132 + 3*64 + 128) * 4)
__global__ __launch_bounds__(256) void k_recur() {
  extern __shared__ float sm[];
  float* S     = sm;                     // 128 x 33 (32 cols + pad)
  float* vn    = S + 128*33;             // 64 x 33
  float* attnS = vn + 64*33;             // 64 x 64
  float* buf   = attnS + 4096;           // 64 x 132: wkcd then rk(=wk rows 1..)
  float* decS  = buf + 64*132;           // 64
  float* edw   = decS + 64;              // exp(dec_last - dec)
  float* edc   = edw + 64;               // exp(dec)
  float* w0    = edc + 64;               // 128: wk row 0

  int blk = blockIdx.x;                  // bh*4 + eg
  int bh = blk >> 2, eg = blk & 3;
  int e0 = eg * 32;
  int b = bh >> 3, h = bh & 7;
  int tid = threadIdx.x;
  int e = tid & 31;

  for (int i = tid; i < 128*33; i += 256) S[i] = 0.0f;
  __syncthreads();

  for (int n = 0; n < Nchunk; n++) {
    size_t tbase = (size_t)bh * Tn + (size_t)n * Cn;
    if (tid < 64) {
      float dv = g_dec[tbase + tid];
      decS[tid] = dv; edc[tid] = expf(dv);
    }
    const float* aG = g_attn + ((size_t)bh * Nchunk + n) * 4096;
    for (int i = tid; i < 4096; i += 256) attnS[i] = aG[i];
    const float* wkcdG = g_wkcd + tbase * HDn;
    for (int i = tid; i < 64*128; i += 256) {
      int c = i >> 7, d = i & 127;
      buf[c*132 + d] = wkcdG[(size_t)c*HDn + d];
    }
    if (tid >= 64 && tid < 192) {
      int d = tid - 64;
      w0[d] = (n == 0) ? 0.0f : g_rk[(tbase - 1) * HDn + d];
    }
    __syncthreads();
    if (tid < 64) edw[tid] = expf(decS[63] - decS[tid]);

    // phase A: vnew = v' - wkcd @ S
    {
      int cg = tid >> 5;
      float acc[8];
      const float* vG = g_v + tbase * HDn;
#pragma unroll
      for (int r = 0; r < 8; r++) acc[r] = vG[(size_t)(cg*8 + r)*HDn + e0 + e];
      for (int d = 0; d < 128; d++) {
        float s = S[d*33 + e];
#pragma unroll
        for (int r = 0; r < 8; r++) acc[r] -= buf[(cg*8 + r)*132 + d] * s;
      }
#pragma unroll
      for (int r = 0; r < 8; r++) vn[(cg*8 + r)*33 + e] = acc[r];
    }
    __syncthreads();

    // reload buf with rk tile (rows also serve as wk rows 1..63 for update)
    {
      const float* rkG = g_rk + tbase * HDn;
      for (int i = tid; i < 64*128; i += 256) {
        int c = i >> 7, d = i & 127;
        buf[c*132 + d] = rkG[(size_t)c*HDn + d];
      }
    }
    __syncthreads();

    // phase B: o = exp(dec)*(rk @ S) + attn @ vnew; write gated output
    {
      int cg = tid >> 5;
      float acc[8];
#pragma unroll
      for (int r = 0; r < 8; r++) acc[r] = 0.0f;
      for (int d = 0; d < 128; d++) {
        float s = S[d*33 + e];
#pragma unroll
        for (int r = 0; r < 8; r++) acc[r] += buf[(cg*8 + r)*132 + d] * s;
      }
#pragma unroll
      for (int r = 0; r < 8; r++) acc[r] *= edc[cg*8 + r];
      for (int j = 0; j < 64; j++) {
        float vv = vn[j*33 + e];
#pragma unroll
        for (int r = 0; r < 8; r++) acc[r] += attnS[(cg*8 + r)*64 + j] * vv;
      }
#pragma unroll
      for (int r = 0; r < 8; r++) {
        int c = cg*8 + r;
        int t = n*Cn + c;
        float gate = g_gate[(size_t)bh*Tn + t];
        g_o[((size_t)b*Tn + t)*Dn + h*HDn + e0 + e] = acc[r] * gate;
      }
    }
    __syncthreads();

    // update: S = S*exp(dec_last) + sum_c wk[c]*exp(dec_last-dec[c]) * vnew[c]
    {
      int dg = tid >> 5;
      float gl = edc[63];
      float acc[16];
#pragma unroll
      for (int r = 0; r < 16; r++) acc[r] = S[(dg*16 + r)*33 + e] * gl;
      for (int c = 0; c < 64; c++) {
        float tv = edw[c] * vn[c*33 + e];
        const float* wrow = (c == 0) ? w0 : &buf[(c-1)*132];
#pragma unroll
        for (int r = 0; r < 16; r++) acc[r] += wrow[dg*16 + r] * tv;
      }
#pragma unroll
      for (int r = 0; r < 16; r++) S[(dg*16 + r)*33 + e] = acc[r];
    }
    __syncthreads();
  }
}

// ---------------- 6) GEMM: out = x + o @ W_out^T ---------------------------
__global__ __launch_bounds__(256) void k_gemm_out(const float* __restrict__ Bw,
                                                  const float* __restrict__ X,
                                                  float* __restrict__ out) {
  __shared__ float As[8][128];
  __shared__ float Bs[8][128];
  int n0 = blockIdx.x * 128;
  int m0 = blockIdx.y * 128;
  int tid = threadIdx.x;
  int tx = tid & 15, ty = tid >> 4;
  float acc[8][8];
#pragma unroll
  for (int i = 0; i < 8; i++)
#pragma unroll
    for (int j = 0; j < 8; j++) acc[i][j] = 0.0f;
  int lrow = tid >> 1, lk4 = (tid & 1) * 4;
  const float* Ap = g_o + (size_t)(m0 + lrow) * Dn + lk4;
  const float* Bp = Bw + (size_t)(n0 + lrow) * Dn + lk4;
  for (int k0 = 0; k0 < Dn; k0 += 8) {
    float4 av = *(const float4*)(Ap + k0);
    float4 bv = *(const float4*)(Bp + k0);
    __syncthreads();
    As[lk4+0][lrow] = av.x; As[lk4+1][lrow] = av.y; As[lk4+2][lrow] = av.z; As[lk4+3][lrow] = av.w;
    Bs[lk4+0][lrow] = bv.x; Bs[lk4+1][lrow] = bv.y; Bs[lk4+2][lrow] = bv.z; Bs[lk4+3][lrow] = bv.w;
    __syncthreads();
#pragma unroll
    for (int kk = 0; kk < 8; kk++) {
      float a[8], b2[8];
      *(float4*)&a[0]  = *(const float4*)&As[kk][ty*8];
      *(float4*)&a[4]  = *(const float4*)&As[kk][ty*8+4];
      *(float4*)&b2[0] = *(const float4*)&Bs[kk][tx*8];
      *(float4*)&b2[4] = *(const float4*)&Bs[kk][tx*8+4];
#pragma unroll
      for (int i = 0; i < 8; i++)
#pragma unroll
        for (int j = 0; j < 8; j++) acc[i][j] += a[i] * b2[j];
    }
  }
#pragma unroll
  for (int i = 0; i < 8; i++) {
    int m = m0 + ty*8 + i;
#pragma unroll
    for (int j = 0; j < 8; j++) {
      int ncol = n0 + tx*8 + j;
      size_t off = (size_t)m * Dn + ncol;
      out[off] = X[off] + acc[i][j];
    }
  }
}

// ---------------------------------------------------------------------------
extern "C" void kernel_launch(void* const* d_in, const int* in_sizes, int n_in,
                              void* d_out, int out_size) {
  (void)in_sizes; (void)n_in; (void)out_size;
  const float* x    = (const float*)d_in[0];
  const float* Ww   = (const float*)d_in[1];
  const float* Wg   = (const float*)d_in[2];
  const float* Wo   = (const float*)d_in[3];
  const float* Wb   = (const float*)d_in[4];
  const float* Wa   = (const float*)d_in[5];
  const float* dtb  = (const float*)d_in[6];
  const float* Alog = (const float*)d_in[7];
  float* out = (float*)d_out;

  cudaFuncSetAttribute(k_chunk, cudaFuncAttributeMaxDynamicSharedMemorySize, K4_SMEM);
  cudaFuncSetAttribute(k_recur, cudaFuncAttributeMaxDynamicSharedMemorySize, K5_SMEM);

  k_proj_small<<<BTn, 256>>>(x, Wg, Wb, Wa, dtb, Alog);
  k_cumsum<<<BHn * Nchunk, 64>>>();
  k_gemm_v<<<dim3(Dn/128, BTn/128), 256>>>(x, Ww);
  k_chunk<<<BHn * Nchunk, 256, K4_SMEM>>>();
  k_recur<<<BHn * 4, 256, K5_SMEM>>>();
  k_gemm_out<<<dim3(Dn/128, BTn/128), 256>>>(Wo, x, out);
}

// round 6
// speedup vs baseline: 1.2512x; 1.2512x over previous
#include <cuda_runtime.h>
#include <math.h>
#include <stdint.h>

#define Bn 4
#define Tn 8192
#define Dn 1024
#define Hn 8
#define HDn 128
#define Cn 64
#define Nchunk 128
#define BTn (Bn*Tn)
#define BHn (Bn*Hn)

// ---------------- scratch (device globals; no cudaMalloc allowed) ----------
__device__ float g_v[(size_t)BTn*Dn];       // v*beta -> v' (in place)
__device__ float g_rk[(size_t)BTn*Dn];      // normalized read keys, (B,H,T,d)
__device__ float g_wkcd[(size_t)BTn*Dn];    // wk_cumdecay, (B,H,T,d)
__device__ float g_o[(size_t)BTn*Dn];       // gated per-head output, (B,T,D)
__device__ float g_attn[(size_t)BHn*Nchunk*Cn*Cn];
__device__ float g_beta[BHn*Tn];            // (B,H,T)
__device__ float g_gate[BHn*Tn];
__device__ float g_dec[BHn*Tn];             // decay, then in-chunk cumsum (in place)

__device__ __forceinline__ float warp_sum(float v) {
#pragma unroll
  for (int o = 16; o > 0; o >>= 1) v += __shfl_xor_sync(0xffffffffu, v, o);
  return v;
}

// ======================= mma.sync tf32 helpers ==============================
__device__ __forceinline__ uint32_t smem_u32(const void* p) {
  uint32_t a;
  asm("{ .reg .u64 t; cvta.to.shared.u64 t, %1; cvt.u32.u64 %0, t; }"
      : "=r"(a) : "l"(p));
  return a;
}

__device__ __forceinline__ uint32_t tf32u(float a) {
  uint32_t r; asm("cvt.rna.tf32.f32 %0, %1;" : "=r"(r) : "f"(a)); return r;
}

__device__ __forceinline__ void mma_tf32(float* c, const uint32_t* a,
                                         const uint32_t* b) {
  asm volatile(
      "mma.sync.aligned.m16n8k8.row.col.f32.tf32.tf32.f32 "
      "{%0,%1,%2,%3}, {%4,%5,%6,%7}, {%8,%9}, {%0,%1,%2,%3};"
      : "+f"(c[0]), "+f"(c[1]), "+f"(c[2]), "+f"(c[3])
      : "r"(a[0]), "r"(a[1]), "r"(a[2]), "r"(a[3]), "r"(b[0]), "r"(b[1]));
}

__device__ __forceinline__ void cp16(uint32_t dst, const void* src) {
  asm volatile("cp.async.cg.shared.global [%0], [%1], 16;"
               :: "r"(dst), "l"(src) : "memory");
}
#define CP_COMMIT() asm volatile("cp.async.commit_group;" ::: "memory")
#define CP_WAIT1() asm volatile("cp.async.wait_group 1;" ::: "memory")
#define CP_WAIT0() asm volatile("cp.async.wait_group 0;" ::: "memory")

// ---------------- 1) per-token projections + rk normalize ------------------
__global__ __launch_bounds__(256) void k_proj_small(
    const float* __restrict__ x, const float* __restrict__ Wg,
    const float* __restrict__ Wb, const float* __restrict__ Wa,
    const float* __restrict__ dtb, const float* __restrict__ Alog) {
  __shared__ float xs[Dn];
  int row = blockIdx.x;                  // b*T + t
  const float* xr = x + (size_t)row * Dn;
  for (int i = threadIdx.x; i < Dn; i += 256) xs[i] = xr[i];
  __syncthreads();
  int h = threadIdx.x >> 5, lane = threadIdx.x & 31;
  const float* wg = Wg + h * Dn;
  const float* wb = Wb + h * Dn;
  const float* wa = Wa + h * Dn;
  float sg = 0.f, sb = 0.f, sa = 0.f;
  for (int i = lane; i < Dn; i += 32) {
    float xv = xs[i];
    sg += xv * wg[i]; sb += xv * wb[i]; sa += xv * wa[i];
  }
  sg = warp_sum(sg); sb = warp_sum(sb); sa = warp_sum(sa);
  float ss = 0.f;
  for (int i = lane; i < HDn; i += 32) { float v = xs[h*HDn + i]; ss += v*v; }
  ss = warp_sum(ss);
  float inv = 1.0f / fmaxf(sqrtf(ss), 1e-12f);
  int b = row >> 13, t = row & (Tn - 1);
  size_t bh = (size_t)b * Hn + h;
  float* rko = g_rk + (bh * Tn + t) * HDn;
  for (int i = lane; i < HDn; i += 32) rko[i] = xs[h*HDn + i] * inv;
  if (lane == 0) {
    g_gate[bh*Tn + t] = 1.0f / (1.0f + expf(-sg));
    g_beta[bh*Tn + t] = 1.0f / (1.0f + expf(-sb));
    float z = sa + dtb[h];
    float sp = (z > 20.0f) ? z : log1pf(expf(z));
    g_dec[bh*Tn + t] = -expf(Alog[h]) * sp;
  }
}

// ---------------- 2) in-chunk cumsum of decay ------------------------------
__global__ void k_cumsum() {
  int idx = blockIdx.x;                  // bh*N + n
  int bh = idx >> 7, n = idx & (Nchunk - 1);
  size_t base = (size_t)bh * Tn + (size_t)n * Cn;
  float v = g_dec[base + threadIdx.x];
  int lane = threadIdx.x & 31, w = threadIdx.x >> 5;
#pragma unroll
  for (int o = 1; o < 32; o <<= 1) {
    float u = __shfl_up_sync(0xffffffffu, v, o);
    if (lane >= o) v += u;
  }
  __shared__ float tot;
  if (w == 0 && lane == 31) tot = v;
  __syncthreads();
  if (w == 1) v += tot;
  g_dec[base + threadIdx.x] = v;
}

// ---------------- 3/6) mma.sync tf32 GEMM (3xTF32 split) -------------------
// C = A @ Bw^T  (A: BT x D rows, Bw: D x D rows; both K-major)
// mode 0: A = Ain (x);  g_v[bhT*128+d] = acc * beta
// mode 1: A = g_o (device symbol, resolved in device code); Out = X + acc
#define KCH 32                            // K per stage
#define ASTRIDE 36                        // padded floats per row
#define STG_F (2*128*ASTRIDE)             // floats per stage (A + B)
#define GM_SMEM (2*STG_F*4)

__global__ __launch_bounds__(256) void k_mma(
    const float* __restrict__ Ain, const float* __restrict__ Bw,
    const float* __restrict__ X, float* __restrict__ Out, int mode) {
  extern __shared__ float sf[];
  uint32_t smb = smem_u32(sf);
  int tid = threadIdx.x, wid = tid >> 5, lane = tid & 31;
  int n0 = blockIdx.x * 128;
  int m0 = blockIdx.y * 128;
  int wm = wid >> 2, wn = wid & 3;       // warp tile: rows wm*64, cols wn*32
  int g = lane >> 2, t = lane & 3;

  // CRITICAL: device-side resolution of the device-global operand.
  const float* A = (mode == 0) ? Ain : (const float*)g_o;

  float acc[4][4][4];
#pragma unroll
  for (int mi = 0; mi < 4; mi++)
#pragma unroll
    for (int ni = 0; ni < 4; ni++)
#pragma unroll
      for (int r = 0; r < 4; r++) acc[mi][ni][r] = 0.0f;

  // cp.async issue for one K-chunk into stage s
  auto issue = [&](int kc, int s) {
    uint32_t base = smb + (uint32_t)s * STG_F * 4;
#pragma unroll
    for (int q = 0; q < 4; q++) {
      int idx = q * 256 + tid;
      int row = idx >> 3, c4 = idx & 7;
      cp16(base + (row * ASTRIDE + c4 * 4) * 4,
           A + (size_t)(m0 + row) * Dn + kc * KCH + c4 * 4);
      cp16(base + (128 * ASTRIDE + row * ASTRIDE + c4 * 4) * 4,
           Bw + (size_t)(n0 + row) * Dn + kc * KCH + c4 * 4);
    }
  };

  const int NC = Dn / KCH;               // 32 chunks
  issue(0, 0); CP_COMMIT();
  for (int kc = 0; kc < NC; kc++) {
    int s = kc & 1;
    if (kc + 1 < NC) { issue(kc + 1, s ^ 1); CP_COMMIT(); CP_WAIT1(); }
    else { CP_WAIT0(); }
    __syncthreads();
    const float* As_ = sf + s * STG_F;
    const float* Bs_ = As_ + 128 * ASTRIDE;
#pragma unroll
    for (int kk = 0; kk < 4; kk++) {
      uint32_t ah[4][4], al[4][4];
#pragma unroll
      for (int mi = 0; mi < 4; mi++) {
        int r0 = wm * 64 + mi * 16 + g;
        float x0 = As_[r0 * ASTRIDE + kk * 8 + t];
        float x1 = As_[(r0 + 8) * ASTRIDE + kk * 8 + t];
        float x2 = As_[r0 * ASTRIDE + kk * 8 + t + 4];
        float x3 = As_[(r0 + 8) * ASTRIDE + kk * 8 + t + 4];
        ah[mi][0] = tf32u(x0); al[mi][0] = tf32u(x0 - __uint_as_float(ah[mi][0]));
        ah[mi][1] = tf32u(x1); al[mi][1] = tf32u(x1 - __uint_as_float(ah[mi][1]));
        ah[mi][2] = tf32u(x2); al[mi][2] = tf32u(x2 - __uint_as_float(ah[mi][2]));
        ah[mi][3] = tf32u(x3); al[mi][3] = tf32u(x3 - __uint_as_float(ah[mi][3]));
      }
      uint32_t bh[4][2], bl[4][2];
#pragma unroll
      for (int ni = 0; ni < 4; ni++) {
        int r0 = wn * 32 + ni * 8 + g;
        float y0 = Bs_[r0 * ASTRIDE + kk * 8 + t];
        float y1 = Bs_[r0 * ASTRIDE + kk * 8 + t + 4];
        bh[ni][0] = tf32u(y0); bl[ni][0] = tf32u(y0 - __uint_as_float(bh[ni][0]));
        bh[ni][1] = tf32u(y1); bl[ni][1] = tf32u(y1 - __uint_as_float(bh[ni][1]));
      }
#pragma unroll
      for (int mi = 0; mi < 4; mi++)
#pragma unroll
        for (int ni = 0; ni < 4; ni++) {
          mma_tf32(acc[mi][ni], ah[mi], bh[ni]);
          mma_tf32(acc[mi][ni], ah[mi], bl[ni]);
          mma_tf32(acc[mi][ni], al[mi], bh[ni]);
        }
    }
    __syncthreads();
  }

  // epilogue
  int h = blockIdx.x;                     // mode 0: 128-wide n-block == head
#pragma unroll
  for (int mi = 0; mi < 4; mi++) {
#pragma unroll
    for (int rr = 0; rr < 2; rr++) {
      int m = m0 + wm * 64 + mi * 16 + g + rr * 8;
      if (mode == 0) {
        int b = m >> 13, tt = m & (Tn - 1);
        size_t bhT = ((size_t)(b * Hn + h)) * Tn + tt;
        float beta = g_beta[bhT];
        float* vout = g_v + bhT * HDn;
#pragma unroll
        for (int ni = 0; ni < 4; ni++) {
          int col = wn * 32 + ni * 8 + 2 * t;
          float2 val;
          val.x = acc[mi][ni][rr * 2 + 0] * beta;
          val.y = acc[mi][ni][rr * 2 + 1] * beta;
          *(float2*)(vout + col) = val;
        }
      } else {
#pragma unroll
        for (int ni = 0; ni < 4; ni++) {
          int ncol = n0 + wn * 32 + ni * 8 + 2 * t;
          size_t off = (size_t)m * Dn + ncol;
          float2 xv = *(const float2*)(X + off);
          float2 val;
          val.x = xv.x + acc[mi][ni][rr * 2 + 0];
          val.y = xv.y + acc[mi][ni][rr * 2 + 1];
          *(float2*)(Out + off) = val;
        }
      }
    }
  }
}

// ---------------- 4) per-chunk: P, M, (I+M)^-1, attn, wkcd, v' -------------
#define K4_SMEM ((64*129 + 2*64*65 + 128 + 4*64) * 4)
__global__ __launch_bounds__(256) void k_chunk() {
  extern __shared__ float smf[];
  float* rbuf  = smf;                    // 64x129: rk tile, then scaled wk, then v
  float* Msm   = rbuf + 64*129;          // 64x65
  float* Asm   = Msm + 64*65;            // 64x65 (P' first, then inverse)
  float* w0    = Asm + 64*65;            // 128: wk row 0
  float* decS  = w0 + 128;
  float* betaS = decS + 64;
  float* facS  = betaS + 64;             // beta_i * exp(dec_i - dec_{i-1})
  float* beS   = facS + 64;

  int cid = blockIdx.x;                  // bh*N + n
  int bh = cid >> 7, n = cid & (Nchunk - 1);
  int tid = threadIdx.x;
  size_t tbase = (size_t)bh * Tn + (size_t)n * Cn;
  const float* rkG = g_rk + tbase * HDn;

  for (int i = tid; i < 64*128; i += 256) {
    int c = i >> 7, d = i & 127;
    rbuf[c*129 + d] = rkG[(size_t)c*HDn + d];
  }
  if (tid < 128) w0[tid] = (n == 0) ? 0.0f : g_rk[(tbase - 1) * HDn + tid];
  if (tid >= 128 && tid < 192) {
    int c = tid - 128;
    float dv = g_dec[tbase + c];
    float bv = g_beta[tbase + c];
    decS[c] = dv; betaS[c] = bv; beS[c] = bv * expf(dv);
  }
  __syncthreads();
  if (tid < 64) facS[tid] = (tid == 0) ? 0.0f : betaS[tid] * expf(decS[tid] - decS[tid-1]);

  // P'[i][j] = (rk_i . wk_j) * exp(dec_i - dec_j), i>=j  -> Asm, also attn out
  float* attnOut = g_attn + (size_t)cid * 4096;
  for (int idx = tid; idx < 4096; idx += 256) {
    int i = idx >> 6, j = idx & 63;
    float aval = 0.0f;
    if (i >= j) {
      const float* ri = &rbuf[i*129];
      const float* wj = (j == 0) ? w0 : &rbuf[(j-1)*129];
      float s = 0.f;
#pragma unroll 4
      for (int d = 0; d < 128; d++) s += ri[d] * wj[d];
      aval = s * expf(decS[i] - decS[j]);
      Asm[i*65 + j] = aval;
    }
    attnOut[idx] = aval;
  }
  __syncthreads();

  // M[i][j] (strict lower) = P'[i-1][j] * beta_i * exp(dec_i - dec_{i-1})
  for (int idx = tid; idx < 4096; idx += 256) {
    int i = idx >> 6, j = idx & 63;
    if (i > j) Msm[i*65 + j] = Asm[(i-1)*65 + j] * facS[i];
  }
  __syncthreads();

  // A := I
  for (int idx = tid; idx < 4096; idx += 256) {
    int i = idx >> 6, j = idx & 63;
    Asm[i*65 + j] = (i == j) ? 1.0f : 0.0f;
  }
  __syncthreads();

  // forward elimination: A = (I+M)^-1 (unit lower triangular)
  for (int i = 0; i < 63; i++) {
    int ncols = i + 1;
    int tot = (63 - i) * ncols;
    for (int idx = tid; idx < tot; idx += 256) {
      int q = idx / ncols;
      int ip = i + 1 + q;
      int k = idx - q * ncols;
      Asm[ip*65 + k] -= Msm[ip*65 + i] * Asm[i*65 + k];
    }
    __syncthreads();
  }

  // scale wk rows in place by beta*exp(dec): wk row j (j>=1) lives at rbuf row j-1
  for (int i = tid; i < 63*128; i += 256) {
    int j = i >> 7, d = i & 127;
    rbuf[j*129 + d] *= beS[j + 1];
  }
  if (tid < 128) w0[tid] *= beS[0];
  __syncthreads();

  // wkcd = A @ (wk_beta * exp(dec))
  {
    int dd = tid & 127, ch = tid >> 7;
    float* outp = g_wkcd + tbase * HDn;
    for (int c = ch; c < 64; c += 2) {
      float acc = Asm[c*65 + 0] * w0[dd];
      for (int j = 1; j <= c; j++) acc += Asm[c*65 + j] * rbuf[(j-1)*129 + dd];
      outp[(size_t)c*HDn + dd] = acc;
    }
  }
  __syncthreads();

  // load v (already *beta) into rbuf
  {
    const float* vG = g_v + tbase * HDn;
    for (int i = tid; i < 64*128; i += 256) {
      int c = i >> 7, d = i & 127;
      rbuf[c*129 + d] = vG[(size_t)c*HDn + d];
    }
  }
  __syncthreads();

  // v' = A @ v (unit diagonal), overwrite g_v
  {
    int dd = tid & 127, ch = tid >> 7;
    float* outp = g_v + tbase * HDn;
    for (int c = ch; c < 64; c += 2) {
      float acc = rbuf[c*129 + dd];
      for (int j = 0; j < c; j++) acc += Asm[c*65 + j] * rbuf[j*129 + dd];
      outp[(size_t)c*HDn + dd] = acc;
    }
  }
}

// ---------------- 5) inter-chunk recurrence, column-split x4 ---------------
#define K5_SMEM ((128*33 + 64*33 + 4096 + 64*132 + 3*64 + 128) * 4)
__global__ __launch_bounds__(256) void k_recur() {
  extern __shared__ float smf[];
  float* S     = smf;                    // 128 x 33 (32 cols + pad)
  float* vn    = S + 128*33;             // 64 x 33
  float* attnS = vn + 64*33;             // 64 x 64
  float* buf   = attnS + 4096;           // 64 x 132: wkcd then rk(=wk rows 1..)
  float* decS  = buf + 64*132;           // 64
  float* edw   = decS + 64;              // exp(dec_last - dec)
  float* edc   = edw + 64;               // exp(dec)
  float* w0    = edc + 64;               // 128: wk row 0

  int blk = blockIdx.x;                  // bh*4 + eg
  int bh = blk >> 2, eg = blk & 3;
  int e0 = eg * 32;
  int b = bh >> 3, h = bh & 7;
  int tid = threadIdx.x;
  int e = tid & 31;

  for (int i = tid; i < 128*33; i += 256) S[i] = 0.0f;
  __syncthreads();

  for (int n = 0; n < Nchunk; n++) {
    size_t tbase = (size_t)bh * Tn + (size_t)n * Cn;
    if (tid < 64) {
      float dv = g_dec[tbase + tid];
      decS[tid] = dv; edc[tid] = expf(dv);
    }
    const float* aG = g_attn + ((size_t)bh * Nchunk + n) * 4096;
    for (int i = tid; i < 4096; i += 256) attnS[i] = aG[i];
    const float* wkcdG = g_wkcd + tbase * HDn;
    for (int i = tid; i < 64*128; i += 256) {
      int c = i >> 7, d = i & 127;
      buf[c*132 + d] = wkcdG[(size_t)c*HDn + d];
    }
    if (tid >= 64 && tid < 192) {
      int d = tid - 64;
      w0[d] = (n == 0) ? 0.0f : g_rk[(tbase - 1) * HDn + d];
    }
    __syncthreads();
    if (tid < 64) edw[tid] = expf(decS[63] - decS[tid]);

    // phase A: vnew = v' - wkcd @ S
    {
      int cg = tid >> 5;
      float acc[8];
      const float* vG = g_v + tbase * HDn;
#pragma unroll
      for (int r = 0; r < 8; r++) acc[r] = vG[(size_t)(cg*8 + r)*HDn + e0 + e];
      for (int d = 0; d < 128; d++) {
        float s = S[d*33 + e];
#pragma unroll
        for (int r = 0; r < 8; r++) acc[r] -= buf[(cg*8 + r)*132 + d] * s;
      }
#pragma unroll
      for (int r = 0; r < 8; r++) vn[(cg*8 + r)*33 + e] = acc[r];
    }
    __syncthreads();

    // reload buf with rk tile (rows also serve as wk rows 1..63 for update)
    {
      const float* rkG = g_rk + tbase * HDn;
      for (int i = tid; i < 64*128; i += 256) {
        int c = i >> 7, d = i & 127;
        buf[c*132 + d] = rkG[(size_t)c*HDn + d];
      }
    }
    __syncthreads();

    // phase B: o = exp(dec)*(rk @ S) + attn @ vnew; write gated output
    {
      int cg = tid >> 5;
      float acc[8];
#pragma unroll
      for (int r = 0; r < 8; r++) acc[r] = 0.0f;
      for (int d = 0; d < 128; d++) {
        float s = S[d*33 + e];
#pragma unroll
        for (int r = 0; r < 8; r++) acc[r] += buf[(cg*8 + r)*132 + d] * s;
      }
#pragma unroll
      for (int r = 0; r < 8; r++) acc[r] *= edc[cg*8 + r];
      for (int j = 0; j < 64; j++) {
        float vv = vn[j*33 + e];
#pragma unroll
        for (int r = 0; r < 8; r++) acc[r] += attnS[(cg*8 + r)*64 + j] * vv;
      }
#pragma unroll
      for (int r = 0; r < 8; r++) {
        int c = cg*8 + r;
        int t = n*Cn + c;
        float gate = g_gate[(size_t)bh*Tn + t];
        g_o[((size_t)b*Tn + t)*Dn + h*HDn + e0 + e] = acc[r] * gate;
      }
    }
    __syncthreads();

    // update: S = S*exp(dec_last) + sum_c wk[c]*exp(dec_last-dec[c]) * vnew[c]
    {
      int dg = tid >> 5;
      float gl = edc[63];
      float acc[16];
#pragma unroll
      for (int r = 0; r < 16; r++) acc[r] = S[(dg*16 + r)*33 + e] * gl;
      for (int c = 0; c < 64; c++) {
        float tv = edw[c] * vn[c*33 + e];
        const float* wrow = (c == 0) ? w0 : &buf[(c-1)*132];
#pragma unroll
        for (int r = 0; r < 16; r++) acc[r] += wrow[dg*16 + r] * tv;
      }
#pragma unroll
      for (int r = 0; r < 16; r++) S[(dg*16 + r)*33 + e] = acc[r];
    }
    __syncthreads();
  }
}

// ---------------------------------------------------------------------------
extern "C" void kernel_launch(void* const* d_in, const int* in_sizes, int n_in,
                              void* d_out, int out_size) {
  (void)in_sizes; (void)n_in; (void)out_size;
  const float* x    = (const float*)d_in[0];
  const float* Ww   = (const float*)d_in[1];
  const float* Wg   = (const float*)d_in[2];
  const float* Wo   = (const float*)d_in[3];
  const float* Wb   = (const float*)d_in[4];
  const float* Wa   = (const float*)d_in[5];
  const float* dtb  = (const float*)d_in[6];
  const float* Alog = (const float*)d_in[7];
  float* out = (float*)d_out;

  cudaFuncSetAttribute(k_mma, cudaFuncAttributeMaxDynamicSharedMemorySize, GM_SMEM);
  cudaFuncSetAttribute(k_chunk, cudaFuncAttributeMaxDynamicSharedMemorySize, K4_SMEM);
  cudaFuncSetAttribute(k_recur, cudaFuncAttributeMaxDynamicSharedMemorySize, K5_SMEM);

  k_proj_small<<<BTn, 256>>>(x, Wg, Wb, Wa, dtb, Alog);
  k_cumsum<<<BHn * Nchunk, 64>>>();
  k_mma<<<dim3(Dn/128, BTn/128), 256, GM_SMEM>>>(x, Ww, x, nullptr, 0);
  k_chunk<<<BHn * Nchunk, 256, K4_SMEM>>>();
  k_recur<<<BHn * 4, 256, K5_SMEM>>>();
  k_mma<<<dim3(Dn/128, BTn/128), 256, GM_SMEM>>>(nullptr, Wo, x, out, 1);
}

// round 7
// speedup vs baseline: 1.4828x; 1.1851x over previous
#include <cuda_runtime.h>
#include <math.h>
#include <stdint.h>

#define Bn 4
#define Tn 8192
#define Dn 1024
#define Hn 8
#define HDn 128
#define Cn 64
#define Nchunk 128
#define BTn (Bn*Tn)
#define BHn (Bn*Hn)

// ---------------- scratch (device globals; no cudaMalloc allowed) ----------
__device__ float g_v[(size_t)BTn*Dn];       // v*beta -> v' (in place)
__device__ float g_rk[(size_t)BTn*Dn];      // normalized read keys, (B,H,T,d)
__device__ float g_wkcd[(size_t)BTn*Dn];    // wk_cumdecay, (B,H,T,d)
__device__ float g_o[(size_t)BTn*Dn];       // gated per-head output, (B,T,D)
__device__ float g_attn[(size_t)BHn*Nchunk*Cn*Cn];
__device__ float g_beta[BHn*Tn];            // (B,H,T)
__device__ float g_gate[BHn*Tn];
__device__ float g_dec[BHn*Tn];             // decay, then in-chunk cumsum (in place)

__device__ __forceinline__ float warp_sum(float v) {
#pragma unroll
  for (int o = 16; o > 0; o >>= 1) v += __shfl_xor_sync(0xffffffffu, v, o);
  return v;
}

// ======================= mma.sync tf32 helpers ==============================
__device__ __forceinline__ uint32_t smem_u32(const void* p) {
  uint32_t a;
  asm("{ .reg .u64 t; cvta.to.shared.u64 t, %1; cvt.u32.u64 %0, t; }"
      : "=r"(a) : "l"(p));
  return a;
}

__device__ __forceinline__ uint32_t tf32u(float a) {
  uint32_t r; asm("cvt.rna.tf32.f32 %0, %1;" : "=r"(r) : "f"(a)); return r;
}

__device__ __forceinline__ void split2(float x, uint32_t& hi, uint32_t& lo) {
  hi = tf32u(x);
  lo = tf32u(x - __uint_as_float(hi));
}

__device__ __forceinline__ void mma_tf32(float* c, const uint32_t* a,
                                         const uint32_t* b) {
  asm volatile(
      "mma.sync.aligned.m16n8k8.row.col.f32.tf32.tf32.f32 "
      "{%0,%1,%2,%3}, {%4,%5,%6,%7}, {%8,%9}, {%0,%1,%2,%3};"
      : "+f"(c[0]), "+f"(c[1]), "+f"(c[2]), "+f"(c[3])
      : "r"(a[0]), "r"(a[1]), "r"(a[2]), "r"(a[3]), "r"(b[0]), "r"(b[1]));
}

__device__ __forceinline__ void cp16(uint32_t dst, const void* src) {
  asm volatile("cp.async.cg.shared.global [%0], [%1], 16;"
               :: "r"(dst), "l"(src) : "memory");
}
#define CP_COMMIT() asm volatile("cp.async.commit_group;" ::: "memory")
#define CP_WAIT1() asm volatile("cp.async.wait_group 1;" ::: "memory")
#define CP_WAIT0() asm volatile("cp.async.wait_group 0;" ::: "memory")

// ---------------- 1) per-token projections + rk normalize ------------------
__global__ __launch_bounds__(256) void k_proj_small(
    const float* __restrict__ x, const float* __restrict__ Wg,
    const float* __restrict__ Wb, const float* __restrict__ Wa,
    const float* __restrict__ dtb, const float* __restrict__ Alog) {
  __shared__ float xs[Dn];
  int row = blockIdx.x;                  // b*T + t
  const float* xr = x + (size_t)row * Dn;
  for (int i = threadIdx.x; i < Dn; i += 256) xs[i] = xr[i];
  __syncthreads();
  int h = threadIdx.x >> 5, lane = threadIdx.x & 31;
  const float* wg = Wg + h * Dn;
  const float* wb = Wb + h * Dn;
  const float* wa = Wa + h * Dn;
  float sg = 0.f, sb = 0.f, sa = 0.f;
  for (int i = lane; i < Dn; i += 32) {
    float xv = xs[i];
    sg += xv * wg[i]; sb += xv * wb[i]; sa += xv * wa[i];
  }
  sg = warp_sum(sg); sb = warp_sum(sb); sa = warp_sum(sa);
  float ss = 0.f;
  for (int i = lane; i < HDn; i += 32) { float v = xs[h*HDn + i]; ss += v*v; }
  ss = warp_sum(ss);
  float inv = 1.0f / fmaxf(sqrtf(ss), 1e-12f);
  int b = row >> 13, t = row & (Tn - 1);
  size_t bh = (size_t)b * Hn + h;
  float* rko = g_rk + (bh * Tn + t) * HDn;
  for (int i = lane; i < HDn; i += 32) rko[i] = xs[h*HDn + i] * inv;
  if (lane == 0) {
    g_gate[bh*Tn + t] = 1.0f / (1.0f + expf(-sg));
    g_beta[bh*Tn + t] = 1.0f / (1.0f + expf(-sb));
    float z = sa + dtb[h];
    float sp = (z > 20.0f) ? z : log1pf(expf(z));
    g_dec[bh*Tn + t] = -expf(Alog[h]) * sp;
  }
}

// ---------------- 2) in-chunk cumsum of decay ------------------------------
__global__ void k_cumsum() {
  int idx = blockIdx.x;                  // bh*N + n
  int bh = idx >> 7, n = idx & (Nchunk - 1);
  size_t base = (size_t)bh * Tn + (size_t)n * Cn;
  float v = g_dec[base + threadIdx.x];
  int lane = threadIdx.x & 31, w = threadIdx.x >> 5;
#pragma unroll
  for (int o = 1; o < 32; o <<= 1) {
    float u = __shfl_up_sync(0xffffffffu, v, o);
    if (lane >= o) v += u;
  }
  __shared__ float tot;
  if (w == 0 && lane == 31) tot = v;
  __syncthreads();
  if (w == 1) v += tot;
  g_dec[base + threadIdx.x] = v;
}

// ---------------- 3/6) mma.sync tf32 GEMM (3xTF32 split) -------------------
#define KCH 32                            // K per stage
#define ASTRIDE 36                        // padded floats per row
#define STG_F (2*128*ASTRIDE)             // floats per stage (A + B)
#define GM_SMEM (2*STG_F*4)

__global__ __launch_bounds__(256) void k_mma(
    const float* __restrict__ Ain, const float* __restrict__ Bw,
    const float* __restrict__ X, float* __restrict__ Out, int mode) {
  extern __shared__ float sf[];
  uint32_t smb = smem_u32(sf);
  int tid = threadIdx.x, wid = tid >> 5, lane = tid & 31;
  int n0 = blockIdx.x * 128;
  int m0 = blockIdx.y * 128;
  int wm = wid >> 2, wn = wid & 3;       // warp tile: rows wm*64, cols wn*32
  int g = lane >> 2, t = lane & 3;

  // device-side resolution of the device-global operand (ATS trap otherwise)
  const float* A = (mode == 0) ? Ain : (const float*)g_o;

  float acc[4][4][4];
#pragma unroll
  for (int mi = 0; mi < 4; mi++)
#pragma unroll
    for (int ni = 0; ni < 4; ni++)
#pragma unroll
      for (int r = 0; r < 4; r++) acc[mi][ni][r] = 0.0f;

  auto issue = [&](int kc, int s) {
    uint32_t base = smb + (uint32_t)s * STG_F * 4;
#pragma unroll
    for (int q = 0; q < 4; q++) {
      int idx = q * 256 + tid;
      int row = idx >> 3, c4 = idx & 7;
      cp16(base + (row * ASTRIDE + c4 * 4) * 4,
           A + (size_t)(m0 + row) * Dn + kc * KCH + c4 * 4);
      cp16(base + (128 * ASTRIDE + row * ASTRIDE + c4 * 4) * 4,
           Bw + (size_t)(n0 + row) * Dn + kc * KCH + c4 * 4);
    }
  };

  const int NC = Dn / KCH;               // 32 chunks
  issue(0, 0); CP_COMMIT();
  for (int kc = 0; kc < NC; kc++) {
    int s = kc & 1;
    if (kc + 1 < NC) { issue(kc + 1, s ^ 1); CP_COMMIT(); CP_WAIT1(); }
    else { CP_WAIT0(); }
    __syncthreads();
    const float* As_ = sf + s * STG_F;
    const float* Bs_ = As_ + 128 * ASTRIDE;
#pragma unroll
    for (int kk = 0; kk < 4; kk++) {
      uint32_t ah[4][4], al[4][4];
#pragma unroll
      for (int mi = 0; mi < 4; mi++) {
        int r0 = wm * 64 + mi * 16 + g;
        split2(As_[r0 * ASTRIDE + kk * 8 + t],          ah[mi][0], al[mi][0]);
        split2(As_[(r0 + 8) * ASTRIDE + kk * 8 + t],    ah[mi][1], al[mi][1]);
        split2(As_[r0 * ASTRIDE + kk * 8 + t + 4],      ah[mi][2], al[mi][2]);
        split2(As_[(r0 + 8) * ASTRIDE + kk * 8 + t + 4],ah[mi][3], al[mi][3]);
      }
      uint32_t bh[4][2], bl[4][2];
#pragma unroll
      for (int ni = 0; ni < 4; ni++) {
        int r0 = wn * 32 + ni * 8 + g;
        split2(Bs_[r0 * ASTRIDE + kk * 8 + t],     bh[ni][0], bl[ni][0]);
        split2(Bs_[r0 * ASTRIDE + kk * 8 + t + 4], bh[ni][1], bl[ni][1]);
      }
#pragma unroll
      for (int mi = 0; mi < 4; mi++)
#pragma unroll
        for (int ni = 0; ni < 4; ni++) {
          mma_tf32(acc[mi][ni], ah[mi], bh[ni]);
          mma_tf32(acc[mi][ni], ah[mi], bl[ni]);
          mma_tf32(acc[mi][ni], al[mi], bh[ni]);
        }
    }
    __syncthreads();
  }

  int h = blockIdx.x;                     // mode 0: 128-wide n-block == head
#pragma unroll
  for (int mi = 0; mi < 4; mi++) {
#pragma unroll
    for (int rr = 0; rr < 2; rr++) {
      int m = m0 + wm * 64 + mi * 16 + g + rr * 8;
      if (mode == 0) {
        int b = m >> 13, tt = m & (Tn - 1);
        size_t bhT = ((size_t)(b * Hn + h)) * Tn + tt;
        float beta = g_beta[bhT];
        float* vout = g_v + bhT * HDn;
#pragma unroll
        for (int ni = 0; ni < 4; ni++) {
          int col = wn * 32 + ni * 8 + 2 * t;
          float2 val;
          val.x = acc[mi][ni][rr * 2 + 0] * beta;
          val.y = acc[mi][ni][rr * 2 + 1] * beta;
          *(float2*)(vout + col) = val;
        }
      } else {
#pragma unroll
        for (int ni = 0; ni < 4; ni++) {
          int ncol = n0 + wn * 32 + ni * 8 + 2 * t;
          size_t off = (size_t)m * Dn + ncol;
          float2 xv = *(const float2*)(X + off);
          float2 val;
          val.x = xv.x + acc[mi][ni][rr * 2 + 0];
          val.y = xv.y + acc[mi][ni][rr * 2 + 1];
          *(float2*)(Out + off) = val;
        }
      }
    }
  }
}

// ---------------- 4) per-chunk: P (mma), M, (I+M)^-1, wkcd/v' (mma) --------
#define RS 132
#define K4_SMEM ((65*RS + 2*64*65 + 4*64) * 4)
__global__ __launch_bounds__(256) void k_chunk() {
  extern __shared__ float smf[];
  float* rbuf  = smf;                    // 65 x 132: row0 = wk0, rows1..64 = rk; later v
  float* Msm   = rbuf + 65*RS;           // 64 x 65
  float* Asm   = Msm + 64*65;            // 64 x 65 (P' lower, then inverse)
  float* decS  = Asm + 64*65;            // 64
  float* betaS = decS + 64;
  float* facS  = betaS + 64;             // beta_i * exp(dec_i - dec_{i-1})
  float* beS   = facS + 64;

  int cid = blockIdx.x;                  // bh*N + n
  int bh = cid >> 7, n = cid & (Nchunk - 1);
  int tid = threadIdx.x;
  int wid = tid >> 5, lane = tid & 31;
  int g = lane >> 2, t = lane & 3;
  size_t tbase = (size_t)bh * Tn + (size_t)n * Cn;
  const float* rkG = g_rk + tbase * HDn;

  for (int i = tid; i < 64*128; i += 256) {
    int c = i >> 7, d = i & 127;
    rbuf[(c+1)*RS + d] = rkG[(size_t)c*HDn + d];
  }
  if (tid < 128) rbuf[tid] = (n == 0) ? 0.0f : g_rk[(tbase - 1) * HDn + tid];
  if (tid >= 128 && tid < 192) {
    int c = tid - 128;
    float dv = g_dec[tbase + c];
    float bv = g_beta[tbase + c];
    decS[c] = dv; betaS[c] = bv; beS[c] = bv * __expf(dv);
  }
  __syncthreads();
  if (tid < 64) facS[tid] = (tid == 0) ? 0.0f
                          : betaS[tid] * __expf(decS[tid] - decS[tid-1]);

  // ---- P[i][j] = rk_i . wk_j via mma (3xTF32); wk_j = rbuf row j ----------
  int wr = wid >> 2, wc = wid & 3;       // 2 x 4 warp grid over 64x64
  float pacc[2][2][4];
#pragma unroll
  for (int mi = 0; mi < 2; mi++)
#pragma unroll
    for (int ni = 0; ni < 2; ni++)
#pragma unroll
      for (int r = 0; r < 4; r++) pacc[mi][ni][r] = 0.0f;

#pragma unroll 2
  for (int ks = 0; ks < 16; ks++) {
    int col = ks*8 + t;
    uint32_t ah[2][4], al[2][4];
#pragma unroll
    for (int mi = 0; mi < 2; mi++) {
      int r0 = 1 + wr*32 + mi*16 + g;
      split2(rbuf[r0*RS + col],         ah[mi][0], al[mi][0]);
      split2(rbuf[(r0+8)*RS + col],     ah[mi][1], al[mi][1]);
      split2(rbuf[r0*RS + col + 4],     ah[mi][2], al[mi][2]);
      split2(rbuf[(r0+8)*RS + col + 4], ah[mi][3], al[mi][3]);
    }
    uint32_t bhf[2][2], blf[2][2];
#pragma unroll
    for (int ni = 0; ni < 2; ni++) {
      int nr = wc*16 + ni*8 + g;
      split2(rbuf[nr*RS + col],     bhf[ni][0], blf[ni][0]);
      split2(rbuf[nr*RS + col + 4], bhf[ni][1], blf[ni][1]);
    }
#pragma unroll
    for (int mi = 0; mi < 2; mi++)
#pragma unroll
      for (int ni = 0; ni < 2; ni++) {
        mma_tf32(pacc[mi][ni], ah[mi], bhf[ni]);
        mma_tf32(pacc[mi][ni], ah[mi], blf[ni]);
        mma_tf32(pacc[mi][ni], al[mi], bhf[ni]);
      }
  }

  // epilogue: attn = P * exp(dec_i - dec_j) masked; also P' lower into Asm
  float* attnOut = g_attn + (size_t)cid * 4096;
#pragma unroll
  for (int mi = 0; mi < 2; mi++)
#pragma unroll
    for (int ni = 0; ni < 2; ni++)
#pragma unroll
      for (int r = 0; r < 4; r++) {
        int i = wr*32 + mi*16 + g + ((r & 2) ? 8 : 0);
        int j = wc*16 + ni*8 + 2*t + (r & 1);
        float aval = 0.0f;
        if (i >= j) {
          aval = pacc[mi][ni][r] * __expf(decS[i] - decS[j]);
          Asm[i*65 + j] = aval;
        }
        attnOut[i*64 + j] = aval;
      }
  __syncthreads();

  // M[i][j] (strict lower) = P'[i-1][j] * beta_i * exp(dec_i - dec_{i-1})
  for (int idx = tid; idx < 4096; idx += 256) {
    int i = idx >> 6, j = idx & 63;
    if (i > j) Msm[i*65 + j] = Asm[(i-1)*65 + j] * facS[i];
  }
  __syncthreads();

  // A := I (also zeros the upper triangle for the dense mma below)
  for (int idx = tid; idx < 4096; idx += 256) {
    int i = idx >> 6, j = idx & 63;
    Asm[i*65 + j] = (i == j) ? 1.0f : 0.0f;
  }
  __syncthreads();

  // forward elimination: A = (I+M)^-1 (unit lower triangular)
  for (int i = 0; i < 63; i++) {
    int ncols = i + 1;
    int tot = (63 - i) * ncols;
    for (int idx = tid; idx < tot; idx += 256) {
      int q = idx / ncols;
      int ip = i + 1 + q;
      int k = idx - q * ncols;
      Asm[ip*65 + k] -= Msm[ip*65 + i] * Asm[i*65 + k];
    }
    __syncthreads();
  }

  // scale wk rows in place: rbuf row j *= beta_j * exp(dec_j)
  for (int i = tid; i < 64*128; i += 256) {
    int j = i >> 7, d = i & 127;
    rbuf[j*RS + d] *= beS[j];
  }
  __syncthreads();

  // C = Asm @ Xs (64x128, K=64), 3xTF32 mma; Xs rows in rbuf (stride RS)
  int wr2 = wid >> 1, wc2 = wid & 1;
  auto triMul = [&](float* outp) {
    float cacc[8][4];
#pragma unroll
    for (int ni = 0; ni < 8; ni++)
#pragma unroll
      for (int r = 0; r < 4; r++) cacc[ni][r] = 0.0f;
#pragma unroll 1
    for (int ks = 0; ks < 8; ks++) {
      int col = ks*8 + t;
      uint32_t ah4[4], al4[4];
      int r0 = wr2*16 + g;
      split2(Asm[r0*65 + col],       ah4[0], al4[0]);
      split2(Asm[(r0+8)*65 + col],   ah4[1], al4[1]);
      split2(Asm[r0*65 + col+4],     ah4[2], al4[2]);
      split2(Asm[(r0+8)*65 + col+4], ah4[3], al4[3]);
#pragma unroll
      for (int ni = 0; ni < 8; ni++) {
        int nn = wc2*64 + ni*8 + g;
        uint32_t bh2[2], bl2[2];
        split2(rbuf[col*RS + nn],       bh2[0], bl2[0]);
        split2(rbuf[(col+4)*RS + nn],   bh2[1], bl2[1]);
        mma_tf32(cacc[ni], ah4, bh2);
        mma_tf32(cacc[ni], ah4, bl2);
        mma_tf32(cacc[ni], al4, bh2);
      }
    }
#pragma unroll
    for (int ni = 0; ni < 8; ni++)
#pragma unroll
      for (int rr = 0; rr < 2; rr++) {
        int c = wr2*16 + g + rr*8;
        int d = wc2*64 + ni*8 + 2*t;
        float2 val;
        val.x = cacc[ni][rr*2 + 0];
        val.y = cacc[ni][rr*2 + 1];
        *(float2*)(outp + (size_t)c*HDn + d) = val;
      }
  };

  // wkcd = A^-1 @ (wk * beta * exp(dec))
  triMul(g_wkcd + tbase * HDn);
  __syncthreads();

  // load v (already *beta) into rbuf rows 0..63
  {
    const float* vG = g_v + tbase * HDn;
    for (int i = tid; i < 64*128; i += 256) {
      int c = i >> 7, d = i & 127;
      rbuf[c*RS + d] = vG[(size_t)c*HDn + d];
    }
  }
  __syncthreads();

  // v' = A^-1 @ v
  triMul(g_v + tbase * HDn);
}

// ---------------- 5) inter-chunk recurrence, column-split x4 ---------------
#define K5_SMEM ((128*33 + 64*33 + 4096 + 64*RS + 65*RS + 3*64) * 4)
__global__ __launch_bounds__(256) void k_recur() {
  extern __shared__ float smf[];
  float* S     = smf;                    // 128 x 33 (32 cols + pad)
  float* vn    = S + 128*33;             // 64 x 33
  float* attnS = vn + 64*33;             // 64 x 64
  float* bufA  = attnS + 4096;           // 64 x 132: wkcd
  float* bufB  = bufA + 64*RS;           // 65 x 132: row0 = wk0, rows1..64 = rk
  float* decS  = bufB + 65*RS;           // 64
  float* edw   = decS + 64;              // exp(dec_last - dec)
  float* edc   = edw + 64;               // exp(dec)

  int blk = blockIdx.x;                  // bh*4 + eg
  int bh = blk >> 2, eg = blk & 3;
  int e0 = eg * 32;
  int b = bh >> 3, h = bh & 7;
  int tid = threadIdx.x;
  int e = tid & 31;

  for (int i = tid; i < 128*33; i += 256) S[i] = 0.0f;
  __syncthreads();

  for (int n = 0; n < Nchunk; n++) {
    size_t tbase = (size_t)bh * Tn + (size_t)n * Cn;
    if (tid < 64) {
      float dv = g_dec[tbase + tid];
      decS[tid] = dv; edc[tid] = __expf(dv);
    }
    const float* aG = g_attn + ((size_t)bh * Nchunk + n) * 4096;
    for (int i = tid; i < 4096; i += 256) attnS[i] = aG[i];
    const float* wkcdG = g_wkcd + tbase * HDn;
    const float* rkG = g_rk + tbase * HDn;
    for (int i = tid; i < 64*128; i += 256) {
      int c = i >> 7, d = i & 127;
      bufA[c*RS + d] = wkcdG[(size_t)c*HDn + d];
      bufB[(c+1)*RS + d] = rkG[(size_t)c*HDn + d];
    }
    if (tid >= 64 && tid < 192) {
      int d = tid - 64;
      bufB[d] = (n == 0) ? 0.0f : g_rk[(tbase - 1) * HDn + d];
    }
    __syncthreads();
    if (tid < 64) edw[tid] = __expf(decS[63] - decS[tid]);

    // fused scan: vnew = v' - wkcd @ S  and  oS = rk @ S
    int cg = tid >> 5;
    float accV[8], accO[8];
    {
      const float* vG = g_v + tbase * HDn;
#pragma unroll
      for (int r = 0; r < 8; r++) {
        accV[r] = vG[(size_t)(cg*8 + r)*HDn + e0 + e];
        accO[r] = 0.0f;
      }
      for (int d = 0; d < 128; d++) {
        float s = S[d*33 + e];
#pragma unroll
        for (int r = 0; r < 8; r++) {
          accV[r] -= bufA[(cg*8 + r)*RS + d] * s;
          accO[r] += bufB[(cg*8 + r + 1)*RS + d] * s;
        }
      }
#pragma unroll
      for (int r = 0; r < 8; r++) vn[(cg*8 + r)*33 + e] = accV[r];
    }
    __syncthreads();

    // o = exp(dec)*oS + attn @ vnew; write gated output
    {
#pragma unroll
      for (int r = 0; r < 8; r++) accO[r] *= edc[cg*8 + r];
      for (int j = 0; j < 64; j++) {
        float vv = vn[j*33 + e];
#pragma unroll
        for (int r = 0; r < 8; r++) accO[r] += attnS[(cg*8 + r)*64 + j] * vv;
      }
#pragma unroll
      for (int r = 0; r < 8; r++) {
        int c = cg*8 + r;
        int t = n*Cn + c;
        float gate = g_gate[(size_t)bh*Tn + t];
        g_o[((size_t)b*Tn + t)*Dn + h*HDn + e0 + e] = accO[r] * gate;
      }
    }

    // update: S = S*exp(dec_last) + sum_c wk[c]*exp(dec_last-dec[c]) * vnew[c]
    {
      int dg = tid >> 5;
      float gl = edc[63];
      float acc[16];
#pragma unroll
      for (int r = 0; r < 16; r++) acc[r] = S[(dg*16 + r)*33 + e] * gl;
      for (int c = 0; c < 64; c++) {
        float tv = edw[c] * vn[c*33 + e];
        const float* wrow = &bufB[c*RS];     // wk_c = bufB row c
#pragma unroll
        for (int r = 0; r < 16; r++) acc[r] += wrow[dg*16 + r] * tv;
      }
#pragma unroll
      for (int r = 0; r < 16; r++) S[(dg*16 + r)*33 + e] = acc[r];
    }
    __syncthreads();
  }
}

// ---------------------------------------------------------------------------
extern "C" void kernel_launch(void* const* d_in, const int* in_sizes, int n_in,
                              void* d_out, int out_size) {
  (void)in_sizes; (void)n_in; (void)out_size;
  const float* x    = (const float*)d_in[0];
  const float* Ww   = (const float*)d_in[1];
  const float* Wg   = (const float*)d_in[2];
  const float* Wo   = (const float*)d_in[3];
  const float* Wb   = (const float*)d_in[4];
  const float* Wa   = (const float*)d_in[5];
  const float* dtb  = (const float*)d_in[6];
  const float* Alog = (const float*)d_in[7];
  float* out = (float*)d_out;

  cudaFuncSetAttribute(k_mma, cudaFuncAttributeMaxDynamicSharedMemorySize, GM_SMEM);
  cudaFuncSetAttribute(k_chunk, cudaFuncAttributeMaxDynamicSharedMemorySize, K4_SMEM);
  cudaFuncSetAttribute(k_recur, cudaFuncAttributeMaxDynamicSharedMemorySize, K5_SMEM);

  k_proj_small<<<BTn, 256>>>(x, Wg, Wb, Wa, dtb, Alog);
  k_cumsum<<<BHn * Nchunk, 64>>>();
  k_mma<<<dim3(Dn/128, BTn/128), 256, GM_SMEM>>>(x, Ww, x, nullptr, 0);
  k_chunk<<<BHn * Nchunk, 256, K4_SMEM>>>();
  k_recur<<<BHn * 4, 256, K5_SMEM>>>();
  k_mma<<<dim3(Dn/128, BTn/128), 256, GM_SMEM>>>(nullptr, Wo, x, out, 1);
}

// round 8
// speedup vs baseline: 2.0215x; 1.3633x over previous
#include <cuda_runtime.h>
#include <math.h>
#include <stdint.h>

#define Bn 4
#define Tn 8192
#define Dn 1024
#define Hn 8
#define HDn 128
#define Cn 64
#define Nchunk 128
#define BTn (Bn*Tn)
#define BHn (Bn*Hn)

// ---------------- scratch (device globals; no cudaMalloc allowed) ----------
__device__ float g_v[(size_t)BTn*Dn];       // v*beta -> v' (in place)
__device__ float g_rk[(size_t)BTn*Dn];      // normalized read keys, (B,H,T,d)
__device__ float g_wkcd[(size_t)BTn*Dn];    // wk_cumdecay, (B,H,T,d)
__device__ float g_o[(size_t)BTn*Dn];       // gated per-head output, (B,T,D)
__device__ float g_attn[(size_t)BHn*Nchunk*Cn*Cn];
__device__ float g_beta[BHn*Tn];            // (B,H,T)
__device__ float g_gate[BHn*Tn];
__device__ float g_dec[BHn*Tn];             // decay, then in-chunk cumsum (in place)

__device__ __forceinline__ float warp_sum(float v) {
#pragma unroll
  for (int o = 16; o > 0; o >>= 1) v += __shfl_xor_sync(0xffffffffu, v, o);
  return v;
}

// ======================= mma.sync tf32 helpers ==============================
__device__ __forceinline__ uint32_t smem_u32(const void* p) {
  uint32_t a;
  asm("{ .reg .u64 t; cvta.to.shared.u64 t, %1; cvt.u32.u64 %0, t; }"
      : "=r"(a) : "l"(p));
  return a;
}

__device__ __forceinline__ uint32_t tf32u(float a) {
  uint32_t r; asm("cvt.rna.tf32.f32 %0, %1;" : "=r"(r) : "f"(a)); return r;
}

__device__ __forceinline__ void split2(float x, uint32_t& hi, uint32_t& lo) {
  hi = tf32u(x);
  lo = tf32u(x - __uint_as_float(hi));
}

__device__ __forceinline__ void mma_tf32(float* c, const uint32_t* a,
                                         const uint32_t* b) {
  asm volatile(
      "mma.sync.aligned.m16n8k8.row.col.f32.tf32.tf32.f32 "
      "{%0,%1,%2,%3}, {%4,%5,%6,%7}, {%8,%9}, {%0,%1,%2,%3};"
      : "+f"(c[0]), "+f"(c[1]), "+f"(c[2]), "+f"(c[3])
      : "r"(a[0]), "r"(a[1]), "r"(a[2]), "r"(a[3]), "r"(b[0]), "r"(b[1]));
}

__device__ __forceinline__ void cp16(uint32_t dst, const void* src) {
  asm volatile("cp.async.cg.shared.global [%0], [%1], 16;"
               :: "r"(dst), "l"(src) : "memory");
}
#define CP_COMMIT() asm volatile("cp.async.commit_group;" ::: "memory")
#define CP_WAIT1() asm volatile("cp.async.wait_group 1;" ::: "memory")
#define CP_WAIT0() asm volatile("cp.async.wait_group 0;" ::: "memory")

// ---------------- 1) per-token projections + rk normalize ------------------
__global__ __launch_bounds__(256) void k_proj_small(
    const float* __restrict__ x, const float* __restrict__ Wg,
    const float* __restrict__ Wb, const float* __restrict__ Wa,
    const float* __restrict__ dtb, const float* __restrict__ Alog) {
  __shared__ float xs[Dn];
  int row = blockIdx.x;                  // b*T + t
  const float* xr = x + (size_t)row * Dn;
  for (int i = threadIdx.x; i < Dn; i += 256) xs[i] = xr[i];
  __syncthreads();
  int h = threadIdx.x >> 5, lane = threadIdx.x & 31;
  const float* wg = Wg + h * Dn;
  const float* wb = Wb + h * Dn;
  const float* wa = Wa + h * Dn;
  float sg = 0.f, sb = 0.f, sa = 0.f;
  for (int i = lane; i < Dn; i += 32) {
    float xv = xs[i];
    sg += xv * wg[i]; sb += xv * wb[i]; sa += xv * wa[i];
  }
  sg = warp_sum(sg); sb = warp_sum(sb); sa = warp_sum(sa);
  float ss = 0.f;
  for (int i = lane; i < HDn; i += 32) { float v = xs[h*HDn + i]; ss += v*v; }
  ss = warp_sum(ss);
  float inv = 1.0f / fmaxf(sqrtf(ss), 1e-12f);
  int b = row >> 13, t = row & (Tn - 1);
  size_t bh = (size_t)b * Hn + h;
  float* rko = g_rk + (bh * Tn + t) * HDn;
  for (int i = lane; i < HDn; i += 32) rko[i] = xs[h*HDn + i] * inv;
  if (lane == 0) {
    g_gate[bh*Tn + t] = 1.0f / (1.0f + expf(-sg));
    g_beta[bh*Tn + t] = 1.0f / (1.0f + expf(-sb));
    float z = sa + dtb[h];
    float sp = (z > 20.0f) ? z : log1pf(expf(z));
    g_dec[bh*Tn + t] = -expf(Alog[h]) * sp;
  }
}

// ---------------- 2) in-chunk cumsum of decay ------------------------------
__global__ void k_cumsum() {
  int idx = blockIdx.x;                  // bh*N + n
  int bh = idx >> 7, n = idx & (Nchunk - 1);
  size_t base = (size_t)bh * Tn + (size_t)n * Cn;
  float v = g_dec[base + threadIdx.x];
  int lane = threadIdx.x & 31, w = threadIdx.x >> 5;
#pragma unroll
  for (int o = 1; o < 32; o <<= 1) {
    float u = __shfl_up_sync(0xffffffffu, v, o);
    if (lane >= o) v += u;
  }
  __shared__ float tot;
  if (w == 0 && lane == 31) tot = v;
  __syncthreads();
  if (w == 1) v += tot;
  g_dec[base + threadIdx.x] = v;
}

// ---------------- 3/6) mma.sync tf32 GEMM (3xTF32 split) -------------------
#define KCH 32                            // K per stage
#define ASTRIDE 36                        // padded floats per row
#define STG_F (2*128*ASTRIDE)             // floats per stage (A + B)
#define GM_SMEM (2*STG_F*4)

__global__ __launch_bounds__(256) void k_mma(
    const float* __restrict__ Ain, const float* __restrict__ Bw,
    const float* __restrict__ X, float* __restrict__ Out, int mode) {
  extern __shared__ float sf[];
  uint32_t smb = smem_u32(sf);
  int tid = threadIdx.x, wid = tid >> 5, lane = tid & 31;
  int n0 = blockIdx.x * 128;
  int m0 = blockIdx.y * 128;
  int wm = wid >> 2, wn = wid & 3;       // warp tile: rows wm*64, cols wn*32
  int g = lane >> 2, t = lane & 3;

  // device-side resolution of the device-global operand (ATS trap otherwise)
  const float* A = (mode == 0) ? Ain : (const float*)g_o;

  float acc[4][4][4];
#pragma unroll
  for (int mi = 0; mi < 4; mi++)
#pragma unroll
    for (int ni = 0; ni < 4; ni++)
#pragma unroll
      for (int r = 0; r < 4; r++) acc[mi][ni][r] = 0.0f;

  auto issue = [&](int kc, int s) {
    uint32_t base = smb + (uint32_t)s * STG_F * 4;
#pragma unroll
    for (int q = 0; q < 4; q++) {
      int idx = q * 256 + tid;
      int row = idx >> 3, c4 = idx & 7;
      cp16(base + (row * ASTRIDE + c4 * 4) * 4,
           A + (size_t)(m0 + row) * Dn + kc * KCH + c4 * 4);
      cp16(base + (128 * ASTRIDE + row * ASTRIDE + c4 * 4) * 4,
           Bw + (size_t)(n0 + row) * Dn + kc * KCH + c4 * 4);
    }
  };

  const int NC = Dn / KCH;               // 32 chunks
  issue(0, 0); CP_COMMIT();
  for (int kc = 0; kc < NC; kc++) {
    int s = kc & 1;
    if (kc + 1 < NC) { issue(kc + 1, s ^ 1); CP_COMMIT(); CP_WAIT1(); }
    else { CP_WAIT0(); }
    __syncthreads();
    const float* As_ = sf + s * STG_F;
    const float* Bs_ = As_ + 128 * ASTRIDE;
#pragma unroll
    for (int kk = 0; kk < 4; kk++) {
      uint32_t ah[4][4], al[4][4];
#pragma unroll
      for (int mi = 0; mi < 4; mi++) {
        int r0 = wm * 64 + mi * 16 + g;
        split2(As_[r0 * ASTRIDE + kk * 8 + t],          ah[mi][0], al[mi][0]);
        split2(As_[(r0 + 8) * ASTRIDE + kk * 8 + t],    ah[mi][1], al[mi][1]);
        split2(As_[r0 * ASTRIDE + kk * 8 + t + 4],      ah[mi][2], al[mi][2]);
        split2(As_[(r0 + 8) * ASTRIDE + kk * 8 + t + 4],ah[mi][3], al[mi][3]);
      }
      uint32_t bh[4][2], bl[4][2];
#pragma unroll
      for (int ni = 0; ni < 4; ni++) {
        int r0 = wn * 32 + ni * 8 + g;
        split2(Bs_[r0 * ASTRIDE + kk * 8 + t],     bh[ni][0], bl[ni][0]);
        split2(Bs_[r0 * ASTRIDE + kk * 8 + t + 4], bh[ni][1], bl[ni][1]);
      }
#pragma unroll
      for (int mi = 0; mi < 4; mi++)
#pragma unroll
        for (int ni = 0; ni < 4; ni++) {
          mma_tf32(acc[mi][ni], ah[mi], bh[ni]);
          mma_tf32(acc[mi][ni], ah[mi], bl[ni]);
          mma_tf32(acc[mi][ni], al[mi], bh[ni]);
        }
    }
    __syncthreads();
  }

  int h = blockIdx.x;                     // mode 0: 128-wide n-block == head
#pragma unroll
  for (int mi = 0; mi < 4; mi++) {
#pragma unroll
    for (int rr = 0; rr < 2; rr++) {
      int m = m0 + wm * 64 + mi * 16 + g + rr * 8;
      if (mode == 0) {
        int b = m >> 13, tt = m & (Tn - 1);
        size_t bhT = ((size_t)(b * Hn + h)) * Tn + tt;
        float beta = g_beta[bhT];
        float* vout = g_v + bhT * HDn;
#pragma unroll
        for (int ni = 0; ni < 4; ni++) {
          int col = wn * 32 + ni * 8 + 2 * t;
          float2 val;
          val.x = acc[mi][ni][rr * 2 + 0] * beta;
          val.y = acc[mi][ni][rr * 2 + 1] * beta;
          *(float2*)(vout + col) = val;
        }
      } else {
#pragma unroll
        for (int ni = 0; ni < 4; ni++) {
          int ncol = n0 + wn * 32 + ni * 8 + 2 * t;
          size_t off = (size_t)m * Dn + ncol;
          float2 xv = *(const float2*)(X + off);
          float2 val;
          val.x = xv.x + acc[mi][ni][rr * 2 + 0];
          val.y = xv.y + acc[mi][ni][rr * 2 + 1];
          *(float2*)(Out + off) = val;
        }
      }
    }
  }
}

// ---------------- 4) per-chunk: P (mma), M, (I+M)^-1, wkcd/v' (mma) --------
#define RS 132
#define K4_SMEM ((65*RS + 2*64*65 + 4*64) * 4)
__global__ __launch_bounds__(256) void k_chunk() {
  extern __shared__ float smf[];
  float* rbuf  = smf;                    // 65 x 132: row0 = wk0, rows1..64 = rk; later v
  float* Msm   = rbuf + 65*RS;           // 64 x 65
  float* Asm   = Msm + 64*65;            // 64 x 65 (P' lower, then inverse)
  float* decS  = Asm + 64*65;            // 64
  float* betaS = decS + 64;
  float* facS  = betaS + 64;             // beta_i * exp(dec_i - dec_{i-1})
  float* beS   = facS + 64;

  int cid = blockIdx.x;                  // bh*N + n
  int bh = cid >> 7, n = cid & (Nchunk - 1);
  int tid = threadIdx.x;
  int wid = tid >> 5, lane = tid & 31;
  int g = lane >> 2, t = lane & 3;
  size_t tbase = (size_t)bh * Tn + (size_t)n * Cn;
  const float* rkG = g_rk + tbase * HDn;

  for (int i = tid; i < 64*128; i += 256) {
    int c = i >> 7, d = i & 127;
    rbuf[(c+1)*RS + d] = rkG[(size_t)c*HDn + d];
  }
  if (tid < 128) rbuf[tid] = (n == 0) ? 0.0f : g_rk[(tbase - 1) * HDn + tid];
  if (tid >= 128 && tid < 192) {
    int c = tid - 128;
    float dv = g_dec[tbase + c];
    float bv = g_beta[tbase + c];
    decS[c] = dv; betaS[c] = bv; beS[c] = bv * __expf(dv);
  }
  __syncthreads();
  if (tid < 64) facS[tid] = (tid == 0) ? 0.0f
                          : betaS[tid] * __expf(decS[tid] - decS[tid-1]);

  // ---- P[i][j] = rk_i . wk_j via mma (3xTF32); wk_j = rbuf row j ----------
  int wr = wid >> 2, wc = wid & 3;       // 2 x 4 warp grid over 64x64
  float pacc[2][2][4];
#pragma unroll
  for (int mi = 0; mi < 2; mi++)
#pragma unroll
    for (int ni = 0; ni < 2; ni++)
#pragma unroll
      for (int r = 0; r < 4; r++) pacc[mi][ni][r] = 0.0f;

#pragma unroll 2
  for (int ks = 0; ks < 16; ks++) {
    int col = ks*8 + t;
    uint32_t ah[2][4], al[2][4];
#pragma unroll
    for (int mi = 0; mi < 2; mi++) {
      int r0 = 1 + wr*32 + mi*16 + g;
      split2(rbuf[r0*RS + col],         ah[mi][0], al[mi][0]);
      split2(rbuf[(r0+8)*RS + col],     ah[mi][1], al[mi][1]);
      split2(rbuf[r0*RS + col + 4],     ah[mi][2], al[mi][2]);
      split2(rbuf[(r0+8)*RS + col + 4], ah[mi][3], al[mi][3]);
    }
    uint32_t bhf[2][2], blf[2][2];
#pragma unroll
    for (int ni = 0; ni < 2; ni++) {
      int nr = wc*16 + ni*8 + g;
      split2(rbuf[nr*RS + col],     bhf[ni][0], blf[ni][0]);
      split2(rbuf[nr*RS + col + 4], bhf[ni][1], blf[ni][1]);
    }
#pragma unroll
    for (int mi = 0; mi < 2; mi++)
#pragma unroll
      for (int ni = 0; ni < 2; ni++) {
        mma_tf32(pacc[mi][ni], ah[mi], bhf[ni]);
        mma_tf32(pacc[mi][ni], ah[mi], blf[ni]);
        mma_tf32(pacc[mi][ni], al[mi], bhf[ni]);
      }
  }

  // epilogue: attn = P * exp(dec_i - dec_j) masked; also P' lower into Asm
  float* attnOut = g_attn + (size_t)cid * 4096;
#pragma unroll
  for (int mi = 0; mi < 2; mi++)
#pragma unroll
    for (int ni = 0; ni < 2; ni++)
#pragma unroll
      for (int r = 0; r < 4; r++) {
        int i = wr*32 + mi*16 + g + ((r & 2) ? 8 : 0);
        int j = wc*16 + ni*8 + 2*t + (r & 1);
        float aval = 0.0f;
        if (i >= j) {
          aval = pacc[mi][ni][r] * __expf(decS[i] - decS[j]);
          Asm[i*65 + j] = aval;
        }
        attnOut[i*64 + j] = aval;
      }
  __syncthreads();

  // M[i][j] (strict lower) = P'[i-1][j] * beta_i * exp(dec_i - dec_{i-1})
  for (int idx = tid; idx < 4096; idx += 256) {
    int i = idx >> 6, j = idx & 63;
    if (i > j) Msm[i*65 + j] = Asm[(i-1)*65 + j] * facS[i];
  }
  __syncthreads();

  // A := I (also zeros the upper triangle for the dense mma below)
  for (int idx = tid; idx < 4096; idx += 256) {
    int i = idx >> 6, j = idx & 63;
    Asm[i*65 + j] = (i == j) ? 1.0f : 0.0f;
  }
  __syncthreads();

  // forward elimination: A = (I+M)^-1 (unit lower triangular)
  for (int i = 0; i < 63; i++) {
    int ncols = i + 1;
    int tot = (63 - i) * ncols;
    for (int idx = tid; idx < tot; idx += 256) {
      int q = idx / ncols;
      int ip = i + 1 + q;
      int k = idx - q * ncols;
      Asm[ip*65 + k] -= Msm[ip*65 + i] * Asm[i*65 + k];
    }
    __syncthreads();
  }

  // scale wk rows in place: rbuf row j *= beta_j * exp(dec_j)
  for (int i = tid; i < 64*128; i += 256) {
    int j = i >> 7, d = i & 127;
    rbuf[j*RS + d] *= beS[j];
  }
  __syncthreads();

  // C = Asm @ Xs (64x128, K=64), 3xTF32 mma; Xs rows in rbuf (stride RS)
  int wr2 = wid >> 1, wc2 = wid & 1;
  auto triMul = [&](float* outp) {
    float cacc[8][4];
#pragma unroll
    for (int ni = 0; ni < 8; ni++)
#pragma unroll
      for (int r = 0; r < 4; r++) cacc[ni][r] = 0.0f;
#pragma unroll 1
    for (int ks = 0; ks < 8; ks++) {
      int col = ks*8 + t;
      uint32_t ah4[4], al4[4];
      int r0 = wr2*16 + g;
      split2(Asm[r0*65 + col],       ah4[0], al4[0]);
      split2(Asm[(r0+8)*65 + col],   ah4[1], al4[1]);
      split2(Asm[r0*65 + col+4],     ah4[2], al4[2]);
      split2(Asm[(r0+8)*65 + col+4], ah4[3], al4[3]);
#pragma unroll
      for (int ni = 0; ni < 8; ni++) {
        int nn = wc2*64 + ni*8 + g;
        uint32_t bh2[2], bl2[2];
        split2(rbuf[col*RS + nn],       bh2[0], bl2[0]);
        split2(rbuf[(col+4)*RS + nn],   bh2[1], bl2[1]);
        mma_tf32(cacc[ni], ah4, bh2);
        mma_tf32(cacc[ni], ah4, bl2);
        mma_tf32(cacc[ni], al4, bh2);
      }
    }
#pragma unroll
    for (int ni = 0; ni < 8; ni++)
#pragma unroll
      for (int rr = 0; rr < 2; rr++) {
        int c = wr2*16 + g + rr*8;
        int d = wc2*64 + ni*8 + 2*t;
        float2 val;
        val.x = cacc[ni][rr*2 + 0];
        val.y = cacc[ni][rr*2 + 1];
        *(float2*)(outp + (size_t)c*HDn + d) = val;
      }
  };

  // wkcd = A^-1 @ (wk * beta * exp(dec))
  triMul(g_wkcd + tbase * HDn);
  __syncthreads();

  // load v (already *beta) into rbuf rows 0..63
  {
    const float* vG = g_v + tbase * HDn;
    for (int i = tid; i < 64*128; i += 256) {
      int c = i >> 7, d = i & 127;
      rbuf[c*RS + d] = vG[(size_t)c*HDn + d];
    }
  }
  __syncthreads();

  // v' = A^-1 @ v
  triMul(g_v + tbase * HDn);
}

// ---------------- 5) inter-chunk recurrence, tensorized --------------------
// S layouts: d-major, stride 40 (B-operand conflict-free: 8*40 % 32 == 8)
#define SS 40
#define ATS 68
#define K5_SMEM ((3*128*SS + 4*64*SS + 64*ATS + 64*RS + 65*RS + 2*64) * 4)
__global__ __launch_bounds__(256) void k_recur() {
  extern __shared__ float smf[];
  float* S      = smf;                   // 128 x 40 fp32
  float* S_hi   = S     + 128*SS;        // tf32 hi copy
  float* S_lo   = S_hi  + 128*SS;        // tf32 lo copy
  float* vn_hi  = S_lo  + 128*SS;        // 64 x 40
  float* vn_lo  = vn_hi + 64*SS;
  float* vns_hi = vn_lo + 64*SS;         // edw-scaled vn
  float* vns_lo = vns_hi+ 64*SS;
  float* attnS  = vns_lo+ 64*SS;         // 64 x 68
  float* bufA   = attnS + 64*ATS;        // 64 x 132 (wkcd)
  float* bufB   = bufA  + 64*RS;         // 65 x 132 (row0=wk0, 1..64=rk)
  float* edwS   = bufB  + 65*RS;         // 64
  float* edcS   = edwS  + 64;            // 64

  uint32_t smb = smem_u32(smf);
  int blk = blockIdx.x;                  // bh*4 + eg
  int bh = blk >> 2, eg = blk & 3;
  int e0 = eg * 32;
  int b = bh >> 3, h = bh & 7;
  int tid = threadIdx.x;
  int wid = tid >> 5, lane = tid & 31;
  int g = lane >> 2, t = lane & 3;

  for (int i = tid; i < 3*128*SS; i += 256) S[i] = 0.0f;
  __syncthreads();

  uint32_t sm_attn = smb + (uint32_t)((attnS - smf) * 4);
  uint32_t sm_bufA = smb + (uint32_t)((bufA - smf) * 4);
  uint32_t sm_bufB = smb + (uint32_t)((bufB - smf) * 4);

  for (int n = 0; n < Nchunk; n++) {
    size_t tbase = (size_t)bh * Tn + (size_t)n * Cn;
    // ---- loads (cp.async) ----
    {
      const float* aG = g_attn + ((size_t)bh * Nchunk + n) * 4096;
      // attn: 4096 floats -> 16 cp16/row layout
#pragma unroll
      for (int q = 0; q < 4; q++) {
        int idx = q * 256 + tid;
        int r = idx >> 4, c4 = idx & 15;
        cp16(sm_attn + (uint32_t)(r * ATS + c4 * 4) * 4, aG + r * 64 + c4 * 4);
      }
      const float* wkcdG = g_wkcd + tbase * HDn;
      const float* rkG = g_rk + tbase * HDn;
#pragma unroll
      for (int q = 0; q < 8; q++) {
        int idx = q * 256 + tid;
        int r = idx >> 5, c4 = idx & 31;
        cp16(sm_bufA + (uint32_t)(r * RS + c4 * 4) * 4,
             wkcdG + (size_t)r * HDn + c4 * 4);
        cp16(sm_bufB + (uint32_t)((r + 1) * RS + c4 * 4) * 4,
             rkG + (size_t)r * HDn + c4 * 4);
      }
      if (tid < 32) {
        if (n == 0) {
          float4 z = make_float4(0.f, 0.f, 0.f, 0.f);
          *(float4*)(bufB + tid * 4) = z;
        } else {
          cp16(sm_bufB + (uint32_t)(tid * 4) * 4,
               g_rk + (tbase - 1) * HDn + tid * 4);
        }
      }
      if (tid < 64) {
        float dv = g_dec[tbase + tid];
        float d63 = g_dec[tbase + 63];
        edcS[tid] = __expf(dv);
        edwS[tid] = __expf(d63 - dv);
      }
      CP_COMMIT(); CP_WAIT0();
    }
    __syncthreads();   // sync 1: tiles + S (from prev chunk) visible

    // ---- phase A: warps 0-3 vnew = v' - wkcd@S ; warps 4-7 oS = rk@S -----
    float acc[4][4];
    int w4 = wid & 3;
    int m0 = w4 * 16;
    bool isV = (wid < 4);
    if (isV) {
      const float* vG = g_v + tbase * HDn;
#pragma unroll
      for (int ni = 0; ni < 4; ni++) {
        int e = ni * 8 + 2 * t;
        float2 p0 = *(const float2*)(vG + (size_t)(m0 + g) * HDn + e0 + e);
        float2 p1 = *(const float2*)(vG + (size_t)(m0 + 8 + g) * HDn + e0 + e);
        acc[ni][0] = p0.x; acc[ni][1] = p0.y;
        acc[ni][2] = p1.x; acc[ni][3] = p1.y;
      }
    } else {
#pragma unroll
      for (int ni = 0; ni < 4; ni++)
#pragma unroll
        for (int r = 0; r < 4; r++) acc[ni][r] = 0.0f;
    }
    {
      const float* Abuf = isV ? bufA : (bufB + RS);  // rk rows offset by 1
      float sgn = isV ? -1.0f : 1.0f;
#pragma unroll 2
      for (int ks = 0; ks < 16; ks++) {
        int k0 = ks * 8;
        uint32_t ah[4], al[4];
        split2(sgn * Abuf[(m0 + g) * RS + k0 + t],         ah[0], al[0]);
        split2(sgn * Abuf[(m0 + 8 + g) * RS + k0 + t],     ah[1], al[1]);
        split2(sgn * Abuf[(m0 + g) * RS + k0 + t + 4],     ah[2], al[2]);
        split2(sgn * Abuf[(m0 + 8 + g) * RS + k0 + t + 4], ah[3], al[3]);
#pragma unroll
        for (int ni = 0; ni < 4; ni++) {
          int nn = ni * 8 + g;
          uint32_t bh2[2], bl2[2];
          bh2[0] = __float_as_uint(S_hi[(k0 + t) * SS + nn]);
          bh2[1] = __float_as_uint(S_hi[(k0 + t + 4) * SS + nn]);
          bl2[0] = __float_as_uint(S_lo[(k0 + t) * SS + nn]);
          bl2[1] = __float_as_uint(S_lo[(k0 + t + 4) * SS + nn]);
          mma_tf32(acc[ni], ah, bh2);
          mma_tf32(acc[ni], ah, bl2);
          mma_tf32(acc[ni], al, bh2);
        }
      }
    }
    if (isV) {
      // write vn hi/lo and edw-scaled vns hi/lo
#pragma unroll
      for (int ni = 0; ni < 4; ni++)
#pragma unroll
        for (int r = 0; r < 4; r++) {
          int c = m0 + g + ((r & 2) ? 8 : 0);
          int e = ni * 8 + 2 * t + (r & 1);
          float v = acc[ni][r];
          uint32_t hh, ll;
          split2(v, hh, ll);
          vn_hi[c * SS + e] = __uint_as_float(hh);
          vn_lo[c * SS + e] = __uint_as_float(ll);
          float vs = v * edwS[c];
          split2(vs, hh, ll);
          vns_hi[c * SS + e] = __uint_as_float(hh);
          vns_lo[c * SS + e] = __uint_as_float(ll);
        }
    } else {
      // scale oS by exp(dec_c)
#pragma unroll
      for (int ni = 0; ni < 4; ni++) {
        acc[ni][0] *= edcS[m0 + g];     acc[ni][1] *= edcS[m0 + g];
        acc[ni][2] *= edcS[m0 + 8 + g]; acc[ni][3] *= edcS[m0 + 8 + g];
      }
    }
    __syncthreads();   // sync 2: vn arrays visible

    if (!isV) {
      // ---- phase B (warps 4-7): o = oS_scaled + attn @ vn; gated store ----
#pragma unroll 1
      for (int ks = 0; ks < 8; ks++) {
        int k0 = ks * 8;
        uint32_t ah[4], al[4];
        split2(attnS[(m0 + g) * ATS + k0 + t],         ah[0], al[0]);
        split2(attnS[(m0 + 8 + g) * ATS + k0 + t],     ah[1], al[1]);
        split2(attnS[(m0 + g) * ATS + k0 + t + 4],     ah[2], al[2]);
        split2(attnS[(m0 + 8 + g) * ATS + k0 + t + 4], ah[3], al[3]);
#pragma unroll
        for (int ni = 0; ni < 4; ni++) {
          int nn = ni * 8 + g;
          uint32_t bh2[2], bl2[2];
          bh2[0] = __float_as_uint(vn_hi[(k0 + t) * SS + nn]);
          bh2[1] = __float_as_uint(vn_hi[(k0 + t + 4) * SS + nn]);
          bl2[0] = __float_as_uint(vn_lo[(k0 + t) * SS + nn]);
          bl2[1] = __float_as_uint(vn_lo[(k0 + t + 4) * SS + nn]);
          mma_tf32(acc[ni], ah, bh2);
          mma_tf32(acc[ni], ah, bl2);
          mma_tf32(acc[ni], al, bh2);
        }
      }
      // gated store to g_o
#pragma unroll
      for (int rr = 0; rr < 2; rr++) {
        int c = m0 + g + rr * 8;
        int tg = n * Cn + c;
        float gate = g_gate[(size_t)bh * Tn + tg];
        float* op = g_o + ((size_t)b * Tn + tg) * Dn + h * HDn + e0;
#pragma unroll
        for (int ni = 0; ni < 4; ni++) {
          float2 val;
          val.x = acc[ni][rr * 2 + 0] * gate;
          val.y = acc[ni][rr * 2 + 1] * gate;
          *(float2*)(op + ni * 8 + 2 * t) = val;
        }
      }
    } else {
      // ---- update (warps 0-3): S = gl*S + wk^T @ vns -----------------------
      int m0u = w4 * 32;
      float acc2[2][4][4];
#pragma unroll
      for (int mi = 0; mi < 2; mi++)
#pragma unroll
        for (int ni = 0; ni < 4; ni++)
#pragma unroll
          for (int r = 0; r < 4; r++) acc2[mi][ni][r] = 0.0f;
#pragma unroll 1
      for (int ks = 0; ks < 8; ks++) {
        int k0 = ks * 8;
        uint32_t ah[2][4], al[2][4];
#pragma unroll
        for (int mi = 0; mi < 2; mi++) {
          int mm = m0u + mi * 16 + g;
          split2(bufB[(k0 + t) * RS + mm],         ah[mi][0], al[mi][0]);
          split2(bufB[(k0 + t) * RS + mm + 8],     ah[mi][1], al[mi][1]);
          split2(bufB[(k0 + t + 4) * RS + mm],     ah[mi][2], al[mi][2]);
          split2(bufB[(k0 + t + 4) * RS + mm + 8], ah[mi][3], al[mi][3]);
        }
#pragma unroll
        for (int ni = 0; ni < 4; ni++) {
          int nn = ni * 8 + g;
          uint32_t bh2[2], bl2[2];
          bh2[0] = __float_as_uint(vns_hi[(k0 + t) * SS + nn]);
          bh2[1] = __float_as_uint(vns_hi[(k0 + t + 4) * SS + nn]);
          bl2[0] = __float_as_uint(vns_lo[(k0 + t) * SS + nn]);
          bl2[1] = __float_as_uint(vns_lo[(k0 + t + 4) * SS + nn]);
#pragma unroll
          for (int mi = 0; mi < 2; mi++) {
            mma_tf32(acc2[mi][ni], ah[mi], bh2);
            mma_tf32(acc2[mi][ni], ah[mi], bl2);
            mma_tf32(acc2[mi][ni], al[mi], bh2);
          }
        }
      }
      float gl = edcS[63];
#pragma unroll
      for (int mi = 0; mi < 2; mi++)
#pragma unroll
        for (int ni = 0; ni < 4; ni++)
#pragma unroll
          for (int r = 0; r < 4; r++) {
            int d = m0u + mi * 16 + g + ((r & 2) ? 8 : 0);
            int e = ni * 8 + 2 * t + (r & 1);
            float sNew = gl * S[d * SS + e] + acc2[mi][ni][r];
            S[d * SS + e] = sNew;
            uint32_t hh, ll;
            split2(sNew, hh, ll);
            S_hi[d * SS + e] = __uint_as_float(hh);
            S_lo[d * SS + e] = __uint_as_float(ll);
          }
    }
    __syncthreads();   // sync 3: S updated; attn/bufs free for next loads
  }
}

// ---------------------------------------------------------------------------
extern "C" void kernel_launch(void* const* d_in, const int* in_sizes, int n_in,
                              void* d_out, int out_size) {
  (void)in_sizes; (void)n_in; (void)out_size;
  const float* x    = (const float*)d_in[0];
  const float* Ww   = (const float*)d_in[1];
  const float* Wg   = (const float*)d_in[2];
  const float* Wo   = (const float*)d_in[3];
  const float* Wb   = (const float*)d_in[4];
  const float* Wa   = (const float*)d_in[5];
  const float* dtb  = (const float*)d_in[6];
  const float* Alog = (const float*)d_in[7];
  float* out = (float*)d_out;

  cudaFuncSetAttribute(k_mma, cudaFuncAttributeMaxDynamicSharedMemorySize, GM_SMEM);
  cudaFuncSetAttribute(k_chunk, cudaFuncAttributeMaxDynamicSharedMemorySize, K4_SMEM);
  cudaFuncSetAttribute(k_recur, cudaFuncAttributeMaxDynamicSharedMemorySize, K5_SMEM);

  k_proj_small<<<BTn, 256>>>(x, Wg, Wb, Wa, dtb, Alog);
  k_cumsum<<<BHn * Nchunk, 64>>>();
  k_mma<<<dim3(Dn/128, BTn/128), 256, GM_SMEM>>>(x, Ww, x, nullptr, 0);
  k_chunk<<<BHn * Nchunk, 256, K4_SMEM>>>();
  k_recur<<<BHn * 4, 256, K5_SMEM>>>();
  k_mma<<<dim3(Dn/128, BTn/128), 256, GM_SMEM>>>(nullptr, Wo, x, out, 1);
}